// round 10
// baseline (speedup 1.0000x reference)
#include <cuda_runtime.h>
#include <cstdint>

#define NN      16384      // N_NODES
#define NP      8192       // N_PARENTS
#define NL      8192       // leaves
#define KW      32
#define H       64
#define VOCAB   100000
#define NCLASS  4

#define WPITCH  65         // smem pitch for scalar-read weight tiles (conflict-free)
#define UPITCH  66         // smem pitch for float2-read U tiles (even, conflict-free)
#define LEAFB   256        // leaf-phase blocks (32 leaves each)
#define FULLM   0xffffffffu
#define MAGIC   0x7f800001u   // sNaN bit pattern: impossible as a finite GRU output

// ---------------- device scratch (no allocations allowed) ----------------
__device__ __align__(16) float g_ET[(size_t)VOCAB * H];   // 25.6 MB  E transposed
__device__ __align__(16) float g_h [(size_t)NN * H];      // 4 MB     node_h (sentinel-init)
__device__ __align__(16) float g_WT[4 * H * H];           // 64 KB    Wz^T,Wr^T,Wh^T,Wa (in,out)
__device__ float g_partial[64 * H];                       // max-reduction partials

__device__ __forceinline__ float sigm(float x) { return 1.f / (1.f + __expf(-x)); }

// poll load: L2-coherent, never hoisted
__device__ __forceinline__ uint2 ldcg_u2(const void* p) {
    uint2 v;
    asm volatile("ld.global.cg.v2.u32 {%0,%1}, [%2];"
                 : "=r"(v.x), "=r"(v.y) : "l"(p) : "memory");
    return v;
}
__device__ __forceinline__ void stcg_f2(void* p, float2 v) {
    asm volatile("st.global.cg.v2.f32 [%0], {%1,%2};"
                 :: "l"(p), "f"(v.x), "f"(v.y) : "memory");
}
__device__ __forceinline__ void stcg_f1(void* p, float v) {
    asm volatile("st.global.cg.f32 [%0], %1;" :: "l"(p), "f"(v) : "memory");
}

// warp-local embedding gather: xe[h]=sum_k xw[k]*E_T[xi[k]][h], lane owns h=2lane,2lane+1
__device__ __forceinline__ float2 embed_row(const float* __restrict__ xw,
                                            const int* __restrict__ xi,
                                            int node, int lane) {
    float w  = __ldg(xw + (size_t)node * KW + lane);
    int   ix = __ldg(xi + (size_t)node * KW + lane);
    float2 acc = make_float2(0.f, 0.f);
#pragma unroll 4
    for (int j = 0; j < 32; j++) {
        int   idx = __shfl_sync(FULLM, ix, j);
        float wj  = __shfl_sync(FULLM, w,  j);
        float2 e = *(const float2*)(&g_ET[(size_t)idx * H + 2 * lane]);
        acc.x += wj * e.x;
        acc.y += wj * e.y;
    }
    return acc;
}

// ---------------- kernel 0: build WT + sentinel-init g_h ----------------
// Wz/Wr/Wh stored transposed WT[h][h2]=W[h2][h] (xe @ W^T); Wa stored DIRECT (xe @ Wa).
__global__ void k_prep(const float* __restrict__ Wz, const float* __restrict__ Wr,
                       const float* __restrict__ Wh, const float* __restrict__ Wa) {
    if (blockIdx.x < 3) {
        __shared__ float t[64][65];
        const float* W = (blockIdx.x == 0) ? Wz : (blockIdx.x == 1) ? Wr : Wh;
        int tid = threadIdx.x;
        for (int i = tid; i < 4096; i += 256) {
            int r = i >> 6, c = i & 63;
            t[r][c] = W[i];
        }
        __syncthreads();
        float* WT = g_WT + blockIdx.x * 4096;
        for (int i = tid; i < 4096; i += 256) {
            int h = i >> 6, h2 = i & 63;
            WT[i] = t[h2][h];
        }
    } else if (blockIdx.x == 3) {
        int tid = threadIdx.x;
        float* WT = g_WT + 3 * 4096;
        for (int i = tid; i < 4096; i += 256)
            WT[i] = Wa[i];
    } else {
        // sentinel-init g_h: 16384*64 floats = 262144 uint4
        int i = (blockIdx.x - 4) * 256 + threadIdx.x;
        if (i < (NN * H / 4))
            ((uint4*)g_h)[i] = make_uint4(MAGIC, MAGIC, MAGIC, MAGIC);
    }
}

// ---------------- kernel 1: transpose E (H, VOCAB) -> (VOCAB, H) ----------------
__global__ void k_transpose(const float* __restrict__ E) {
    __shared__ float sm[64][33];
    int v0 = blockIdx.x * 32;
    int tid = threadIdx.x;
    int vv = tid & 31, hh = tid >> 5;
#pragma unroll
    for (int h0 = 0; h0 < 64; h0 += 8)
        sm[h0 + hh][vv] = E[(size_t)(h0 + hh) * VOCAB + v0 + vv];
    __syncthreads();
#pragma unroll
    for (int i = tid; i < 2048; i += 256) {
        int v = i >> 6, h = i & 63;
        g_ET[(size_t)(v0 + v) * H + h] = sm[h][v];
    }
}

// ---------------- kernel 2: persistent main (embed + leaf + parent GRU) ----------------
// Embedding is warp-local (no g_xe): leaf blocks gather their 32 leaves' xe straight
// into smem; parent warps gather their own xe inline before the child polls.
// Sync is data-as-flag on g_h. Deadlock-free: embed/leaf phases terminate
// unconditionally; parent deps point to strictly smaller node indices; grid co-resident.
__global__ void __launch_bounds__(256, 4) k_main(const float* __restrict__ Uz,
                                                 const float* __restrict__ Ur,
                                                 const float* __restrict__ Uh,
                                                 const int*   __restrict__ tree,
                                                 const float* __restrict__ Wz,
                                                 const float* __restrict__ Wh,
                                                 const float* __restrict__ bz,
                                                 const float* __restrict__ br,
                                                 const float* __restrict__ bh,
                                                 const float* __restrict__ xw,
                                                 const int*   __restrict__ xi) {
    extern __shared__ float sm[];
    int tid = threadIdx.x;
    int wid = tid >> 5, lane = tid & 31;

    // ================= leaf phase (blocks 0..LEAFB-1) =================
    if (blockIdx.x < LEAFB) {
        float* sW = sm;                         // 2 * 64 * WPITCH
        float* sb = sW + 2 * 64 * WPITCH;       // 2 * 64
        float* sx = sb + 2 * 64;                // 32 * 64

        for (int m = 0; m < 2; m++) {
            const float* W = m ? Wh : Wz;
            for (int i = tid; i < 4096; i += 256) {
                int h2 = i >> 6, h = i & 63;
                sW[m * 64 * WPITCH + h * WPITCH + h2] = W[i];
            }
        }
        if (tid < 64) { sb[tid] = bz[tid]; sb[64 + tid] = bh[tid]; }

        int base = blockIdx.x * 32;
        // embed 32 leaves straight into smem: warp-per-leaf, 4 passes
#pragma unroll
        for (int pass = 0; pass < 4; pass++) {
            int l = pass * 8 + wid;             // local leaf 0..31
            float2 acc = embed_row(xw, xi, base + l, lane);
            ((float2*)(sx + l * 64))[lane] = acc;
        }
        __syncthreads();

        int h2 = tid & 63, grp = tid >> 6;
        const float* x0 = sx + grp * 8 * 64;
        float az[8] = {0,0,0,0,0,0,0,0}, ah[8] = {0,0,0,0,0,0,0,0};
#pragma unroll 4
        for (int h = 0; h < 64; h++) {
            float wz = sW[h * WPITCH + h2];
            float wh = sW[64 * WPITCH + h * WPITCH + h2];
#pragma unroll
            for (int nb = 0; nb < 8; nb++) {
                float x = x0[nb * 64 + h];
                az[nb] += x * wz; ah[nb] += x * wh;
            }
        }
#pragma unroll
        for (int nb = 0; nb < 8; nb++) {
            int gn = base + grp * 8 + nb;
            float z = sigm(az[nb] + sb[h2]);
            float c = tanhf(ah[nb] + sb[64 + h2]);
            stcg_f1(&g_h[(size_t)gn * H + h2], (1.f - z) * c);   // publishes itself
        }
        __syncthreads();                        // before smem reuse below
    }

    // ================= parent phase (all blocks) =================
    float* sU = sm;                          // 3 * 64 * UPITCH, input-major (U^T)
    float* sv = sU + 3 * 64 * UPITCH;        // 8 warps * 64

    const float* Us[3] = {Uz, Ur, Uh};
    for (int m = 0; m < 3; m++) {
        const float* U = Us[m];
        for (int i = tid; i < 4096; i += 256) {
            int h2 = i >> 6, h = i & 63;
            sU[m * 64 * UPITCH + h * UPITCH + h2] = U[i];
        }
    }
    __syncthreads();

    int gwarp = blockIdx.x * 8 + wid;
    int nwarp = gridDim.x * 8;
    float* svw = sv + wid * 64;
    const float* sUz = sU;
    const float* sUr = sU + 64 * UPITCH;
    const float* sUh = sU + 2 * 64 * UPITCH;

    float2 bz2 = __ldg((const float2*)bz + lane);
    float2 br2 = __ldg((const float2*)br + lane);
    float2 bh2 = __ldg((const float2*)bh + lane);

    for (int p = gwarp; p < NP; p += nwarp) {
        const int* tr = tree + (size_t)p * 5;
        int c0 = __ldg(tr + 0), c1 = __ldg(tr + 1), c2 = __ldg(tr + 2), c3 = __ldg(tr + 3);

        // ---- inline embed of this parent's xe (hidden before the polls) ----
        float2 xe2 = embed_row(xw, xi, NL + p, lane);

        // ---- fused A precompute: az/ar/ah = xe@W^T + b ; aq = xe@Wa ----
        float2 az = bz2, ar = br2, ah = bh2, aq = make_float2(0.f, 0.f);
#pragma unroll 8
        for (int h = 0; h < 64; h++) {
            float b = __shfl_sync(FULLM, (h & 1) ? xe2.y : xe2.x, h >> 1);
            float2 wz = __ldg((const float2*)(g_WT            + h * 64) + lane);
            float2 wr = __ldg((const float2*)(g_WT + 1 * 4096 + h * 64) + lane);
            float2 wh = __ldg((const float2*)(g_WT + 2 * 4096 + h * 64) + lane);
            float2 wa = __ldg((const float2*)(g_WT + 3 * 4096 + h * 64) + lane);
            az.x += b * wz.x; az.y += b * wz.y;
            ar.x += b * wr.x; ar.y += b * wr.y;
            ah.x += b * wh.x; ah.y += b * wh.y;
            aq.x += b * wa.x; aq.y += b * wa.y;
        }

        // ---- data-as-flag poll: each lane waits on its own 8B of each child ----
        const void* p0 = (const uint2*)(g_h + (size_t)(c0 < 0 ? 0 : c0) * H) + lane;
        const void* p1 = (const uint2*)(g_h + (size_t)(c1 < 0 ? 0 : c1) * H) + lane;
        const void* p2 = (const uint2*)(g_h + (size_t)(c2 < 0 ? 0 : c2) * H) + lane;
        const void* p3 = (const uint2*)(g_h + (size_t)(c3 < 0 ? 0 : c3) * H) + lane;
        uint2 v0, v1, v2, v3;
        bool r0 = (c0 < 0), r1 = (c1 < 0), r2 = (c2 < 0), r3 = (c3 < 0);
        for (;;) {
            if (!r0) { v0 = ldcg_u2(p0); r0 = (v0.x != MAGIC) && (v0.y != MAGIC); }
            if (!r1) { v1 = ldcg_u2(p1); r1 = (v1.x != MAGIC) && (v1.y != MAGIC); }
            if (!r2) { v2 = ldcg_u2(p2); r2 = (v2.x != MAGIC) && (v2.y != MAGIC); }
            if (!r3) { v3 = ldcg_u2(p3); r3 = (v3.x != MAGIC) && (v3.y != MAGIC); }
            if (r0 && r1 && r2 && r3) break;
            __nanosleep(20);
        }
        float2 ch0 = (c0 >= 0) ? make_float2(__uint_as_float(v0.x), __uint_as_float(v0.y)) : make_float2(0.f, 0.f);
        float2 ch1 = (c1 >= 0) ? make_float2(__uint_as_float(v1.x), __uint_as_float(v1.y)) : make_float2(0.f, 0.f);
        float2 ch2 = (c2 >= 0) ? make_float2(__uint_as_float(v2.x), __uint_as_float(v2.y)) : make_float2(0.f, 0.f);
        float2 ch3 = (c3 >= 0) ? make_float2(__uint_as_float(v3.x), __uint_as_float(v3.y)) : make_float2(0.f, 0.f);

        // attention logits l_j = sigmoid(q . child_j)
        float q0 = aq.x * ch0.x + aq.y * ch0.y;
        float q1 = aq.x * ch1.x + aq.y * ch1.y;
        float q2 = aq.x * ch2.x + aq.y * ch2.y;
        float q3 = aq.x * ch3.x + aq.y * ch3.y;
#pragma unroll
        for (int o = 16; o > 0; o >>= 1) {
            q0 += __shfl_xor_sync(FULLM, q0, o);
            q1 += __shfl_xor_sync(FULLM, q1, o);
            q2 += __shfl_xor_sync(FULLM, q2, o);
            q3 += __shfl_xor_sync(FULLM, q3, o);
        }
        float l0 = (c0 >= 0) ? sigm(q0) : -1e30f;
        float l1 = (c1 >= 0) ? sigm(q1) : -1e30f;
        float l2 = (c2 >= 0) ? sigm(q2) : -1e30f;
        float l3 = (c3 >= 0) ? sigm(q3) : -1e30f;
        float mx = fmaxf(fmaxf(l0, l1), fmaxf(l2, l3));
        float a0 = (c0 >= 0) ? __expf(l0 - mx) : 0.f;
        float a1 = (c1 >= 0) ? __expf(l1 - mx) : 0.f;
        float a2 = (c2 >= 0) ? __expf(l2 - mx) : 0.f;
        float a3 = (c3 >= 0) ? __expf(l3 - mx) : 0.f;
        float inv = 1.f / (a0 + a1 + a2 + a3);
        a0 *= inv; a1 *= inv; a2 *= inv; a3 *= inv;

        float2 ht;
        ht.x = a0 * ch0.x + a1 * ch1.x + a2 * ch2.x + a3 * ch3.x;
        ht.y = a0 * ch0.y + a1 * ch1.y + a2 * ch2.y + a3 * ch3.y;

        ((float2*)svw)[lane] = ht;
        __syncwarp();

        // z/r GEMVs: two 32-deep accumulator chains
        float2 accz0 = make_float2(0.f, 0.f), accz1 = make_float2(0.f, 0.f);
        float2 accr0 = make_float2(0.f, 0.f), accr1 = make_float2(0.f, 0.f);
#pragma unroll 4
        for (int hp = 0; hp < 32; hp++) {
            float  b0  = svw[hp];
            float  b1  = svw[hp + 32];
            float2 uzA = *(const float2*)(sUz + hp        * UPITCH + 2 * lane);
            float2 uzB = *(const float2*)(sUz + (hp + 32) * UPITCH + 2 * lane);
            float2 urA = *(const float2*)(sUr + hp        * UPITCH + 2 * lane);
            float2 urB = *(const float2*)(sUr + (hp + 32) * UPITCH + 2 * lane);
            accz0.x += b0 * uzA.x; accz0.y += b0 * uzA.y;
            accz1.x += b1 * uzB.x; accz1.y += b1 * uzB.y;
            accr0.x += b0 * urA.x; accr0.y += b0 * urA.y;
            accr1.x += b1 * urB.x; accr1.y += b1 * urB.y;
        }
        float2 z = make_float2(sigm(az.x + accz0.x + accz1.x), sigm(az.y + accz0.y + accz1.y));
        float2 r = make_float2(sigm(ar.x + accr0.x + accr1.x), sigm(ar.y + accr0.y + accr1.y));

        __syncwarp();
        ((float2*)svw)[lane] = make_float2(r.x * ht.x, r.y * ht.y);
        __syncwarp();

        float2 accc0 = make_float2(0.f, 0.f), accc1 = make_float2(0.f, 0.f);
#pragma unroll 4
        for (int hp = 0; hp < 32; hp++) {
            float  b0  = svw[hp];
            float  b1  = svw[hp + 32];
            float2 uhA = *(const float2*)(sUh + hp        * UPITCH + 2 * lane);
            float2 uhB = *(const float2*)(sUh + (hp + 32) * UPITCH + 2 * lane);
            accc0.x += b0 * uhA.x; accc0.y += b0 * uhA.y;
            accc1.x += b1 * uhB.x; accc1.y += b1 * uhB.y;
        }
        float2 cv = make_float2(tanhf(ah.x + accc0.x + accc1.x), tanhf(ah.y + accc0.y + accc1.y));
        float2 hv;
        hv.x = z.x * ht.x + (1.f - z.x) * cv.x;
        hv.y = z.y * ht.y + (1.f - z.y) * cv.y;
        stcg_f2((float2*)(g_h + (size_t)(NL + p) * H) + lane, hv);   // publishes itself
    }
}

// ---------------- kernel 5: per-column max over parents (partial) ----------------
__global__ void k_rmax() {
    __shared__ float sred[4][64];
    int tid = threadIdx.x;               // 256
    int h2 = tid & 63, g = tid >> 6;
    int p0 = blockIdx.x * 128;
    float m = -1e30f;
    for (int r = g; r < 128; r += 4)
        m = fmaxf(m, g_h[(size_t)(NL + p0 + r) * H + h2]);
    sred[g][h2] = m;
    __syncthreads();
    if (tid < 64) {
        float mm = fmaxf(fmaxf(sred[0][tid], sred[1][tid]),
                         fmaxf(sred[2][tid], sred[3][tid]));
        g_partial[blockIdx.x * 64 + tid] = mm;
    }
}

// ---------------- kernel 6: final max + logits + softmax ----------------
__global__ void k_final(const float* __restrict__ Wout, const float* __restrict__ bout,
                        float* __restrict__ out) {
    __shared__ float fm[64];
    __shared__ float lg[4];
    int tid = threadIdx.x;               // 64
    float m = -1e30f;
    for (int b = 0; b < 64; b++) m = fmaxf(m, g_partial[b * 64 + tid]);
    fm[tid] = m;
    __syncthreads();
    if (tid < NCLASS) {
        float s = bout[tid];
        for (int h = 0; h < 64; h++) s += Wout[tid * 64 + h] * fm[h];
        lg[tid] = s;
    }
    __syncthreads();
    if (tid == 0) {
        float mx = fmaxf(fmaxf(lg[0], lg[1]), fmaxf(lg[2], lg[3]));
        float e0 = __expf(lg[0] - mx), e1 = __expf(lg[1] - mx);
        float e2 = __expf(lg[2] - mx), e3 = __expf(lg[3] - mx);
        float s = e0 + e1 + e2 + e3;
        out[0] = e0 / s; out[1] = e1 / s; out[2] = e2 / s; out[3] = e3 / s;
    }
}

// ---------------- launch ----------------
extern "C" void kernel_launch(void* const* d_in, const int* in_sizes, int n_in,
                              void* d_out, int out_size) {
    const float* x_word  = (const float*)d_in[0];
    const int*   x_index = (const int*)  d_in[1];
    const int*   tree    = (const int*)  d_in[2];
    const float* E       = (const float*)d_in[3];
    const float* Wz      = (const float*)d_in[4];
    const float* Uz      = (const float*)d_in[5];
    const float* bz      = (const float*)d_in[6];
    const float* Wr      = (const float*)d_in[7];
    const float* Ur      = (const float*)d_in[8];
    const float* br      = (const float*)d_in[9];
    const float* Wh      = (const float*)d_in[10];
    const float* Uh      = (const float*)d_in[11];
    const float* bh      = (const float*)d_in[12];
    const float* Wa      = (const float*)d_in[13];
    const float* Wout    = (const float*)d_in[14];
    const float* bout    = (const float*)d_in[15];
    float* out = (float*)d_out;

    const int smemMain = (3 * 64 * UPITCH + 8 * 64) * 4;            // 52736 B
    cudaFuncSetAttribute(k_main, cudaFuncAttributeMaxDynamicSharedMemorySize, smemMain);

    int dev = 0;
    cudaGetDevice(&dev);
    int sms = 0;
    if (cudaDeviceGetAttribute(&sms, cudaDevAttrMultiProcessorCount, dev) != cudaSuccess || sms <= 0)
        sms = 148;
    int nb = 0;
    if (cudaOccupancyMaxActiveBlocksPerMultiprocessor(&nb, k_main, 256, smemMain) != cudaSuccess || nb < 1)
        nb = 1;
    int pgrid = sms * nb;                  // guaranteed co-resident
    if (pgrid > NP / 8) pgrid = NP / 8;
    if (pgrid < LEAFB) pgrid = LEAFB;      // all leaf tiles must be covered
    if (pgrid < 1) pgrid = 1;

    k_prep<<<4 + (NN * H / 4 + 255) / 256, 256>>>(Wz, Wr, Wh, Wa);
    k_transpose<<<3125, 256>>>(E);
    k_main<<<pgrid, 256, smemMain>>>(Uz, Ur, Uh, tree, Wz, Wh, bz, br, bh,
                                     x_word, x_index);
    k_rmax<<<64, 256>>>();
    k_final<<<1, 64>>>(Wout, bout, out);
}

// round 11
// speedup vs baseline: 1.3492x; 1.3492x over previous
#include <cuda_runtime.h>
#include <cstdint>

#define NN      16384      // N_NODES
#define NP      8192       // N_PARENTS
#define NL      8192       // leaves
#define KW      32
#define H       64
#define VOCAB   100000
#define NCLASS  4

#define WPITCH  65         // smem pitch for scalar-read weight tiles (conflict-free)
#define LEAFB   256        // leaf-phase blocks (32 leaves each)
#define FULLM   0xffffffffu
#define MAGIC   0x7f800001u   // sNaN bit pattern: impossible as a finite GRU output

// ---------------- device scratch (no allocations allowed) ----------------
__device__ __align__(16) float g_ET[(size_t)VOCAB * H];   // 25.6 MB  E transposed
__device__ __align__(16) float g_xe[(size_t)NN * H];      // 4 MB     xe
__device__ __align__(16) float g_h [(size_t)NN * H];      // 4 MB     node_h (sentinel-init)
__device__ __align__(16) float g_WT[4 * H * H];           // 64 KB    Wz^T,Wr^T,Wh^T,Wa (in,out)
__device__ float g_partial[1024 * H];                     // per-block max partials

__device__ __forceinline__ float sigm(float x) { return 1.f / (1.f + __expf(-x)); }

// poll load: L2-coherent, never hoisted
__device__ __forceinline__ uint2 ldcg_u2(const void* p) {
    uint2 v;
    asm volatile("ld.global.cg.v2.u32 {%0,%1}, [%2];"
                 : "=r"(v.x), "=r"(v.y) : "l"(p) : "memory");
    return v;
}
__device__ __forceinline__ void stcg_f2(void* p, float2 v) {
    asm volatile("st.global.cg.v2.f32 [%0], {%1,%2};"
                 :: "l"(p), "f"(v.x), "f"(v.y) : "memory");
}
__device__ __forceinline__ void stcg_f1(void* p, float v) {
    asm volatile("st.global.cg.f32 [%0], %1;" :: "l"(p), "f"(v) : "memory");
}

// ---------------- kernel 0: build WT + sentinel-init g_h ----------------
// Wz/Wr/Wh stored transposed WT[h][h2]=W[h2][h] (xe @ W^T); Wa stored DIRECT (xe @ Wa).
__global__ void k_prep(const float* __restrict__ Wz, const float* __restrict__ Wr,
                       const float* __restrict__ Wh, const float* __restrict__ Wa) {
    if (blockIdx.x < 3) {
        __shared__ float t[64][65];
        const float* W = (blockIdx.x == 0) ? Wz : (blockIdx.x == 1) ? Wr : Wh;
        int tid = threadIdx.x;
        for (int i = tid; i < 4096; i += 256) {
            int r = i >> 6, c = i & 63;
            t[r][c] = W[i];
        }
        __syncthreads();
        float* WT = g_WT + blockIdx.x * 4096;
        for (int i = tid; i < 4096; i += 256) {
            int h = i >> 6, h2 = i & 63;
            WT[i] = t[h2][h];
        }
    } else if (blockIdx.x == 3) {
        int tid = threadIdx.x;
        float* WT = g_WT + 3 * 4096;
        for (int i = tid; i < 4096; i += 256)
            WT[i] = Wa[i];
    } else {
        // sentinel-init g_h: 16384*64 floats = 262144 uint4
        int i = (blockIdx.x - 4) * 256 + threadIdx.x;
        if (i < (NN * H / 4))
            ((uint4*)g_h)[i] = make_uint4(MAGIC, MAGIC, MAGIC, MAGIC);
    }
}

// ---------------- kernel 1: transpose E (H, VOCAB) -> (VOCAB, H) ----------------
__global__ void k_transpose(const float* __restrict__ E) {
    __shared__ float sm[64][33];
    int v0 = blockIdx.x * 32;
    int tid = threadIdx.x;
    int vv = tid & 31, hh = tid >> 5;
#pragma unroll
    for (int h0 = 0; h0 < 64; h0 += 8)
        sm[h0 + hh][vv] = E[(size_t)(h0 + hh) * VOCAB + v0 + vv];
    __syncthreads();
#pragma unroll
    for (int i = tid; i < 2048; i += 256) {
        int v = i >> 6, h = i & 63;
        g_ET[(size_t)(v0 + v) * H + h] = sm[h][v];
    }
}

// ---------------- kernel 2: xe[n,h] = sum_k x_word[n,k] * E_T[idx[n,k], h] ----------------
__global__ void __launch_bounds__(256) k_embed(const float* __restrict__ xw,
                                               const int* __restrict__ xi) {
    int warp = (blockIdx.x * blockDim.x + threadIdx.x) >> 5;
    int lane = threadIdx.x & 31;
    if (warp >= NN) return;
    float w  = xw[warp * KW + lane];
    int   ix = xi[warp * KW + lane];
    float2 acc = make_float2(0.f, 0.f);
#pragma unroll 4
    for (int j = 0; j < 32; j++) {
        int   idx = __shfl_sync(FULLM, ix, j);
        float wj  = __shfl_sync(FULLM, w,  j);
        float2 e = *(const float2*)(&g_ET[(size_t)idx * H + 2 * lane]);
        acc.x += wj * e.x;
        acc.y += wj * e.y;
    }
    *(float2*)(&g_xe[(size_t)warp * H + 2 * lane]) = acc;
}

// ---------------- kernel 3: persistent main (leaf phase + parent GRU + fused max) ----------------
// Sync is data-as-flag on g_h. Deadlock-free: leaf phase terminates unconditionally;
// parent deps point to strictly smaller node indices; full grid co-resident.
// U matrices stored in smem as 2x2 tiles for LDS.128 inner loops:
//   sU4[m][hp][c] (float4) = { U[2c][2hp], U[2c+1][2hp], U[2c][2hp+1], U[2c+1][2hp+1] }
__global__ void __launch_bounds__(256, 4) k_main(const float* __restrict__ Uz,
                                                 const float* __restrict__ Ur,
                                                 const float* __restrict__ Uh,
                                                 const int*   __restrict__ tree,
                                                 const float* __restrict__ Wz,
                                                 const float* __restrict__ Wh,
                                                 const float* __restrict__ bz,
                                                 const float* __restrict__ br,
                                                 const float* __restrict__ bh) {
    extern __shared__ float sm[];
    int tid = threadIdx.x;
    int wid = tid >> 5, lane = tid & 31;

    // ================= leaf phase (blocks 0..LEAFB-1) =================
    if (blockIdx.x < LEAFB) {
        float* sW = sm;                         // 2 * 64 * WPITCH
        float* sb = sW + 2 * 64 * WPITCH;       // 2 * 64
        float* sx = sb + 2 * 64;                // 32 * 64

        for (int m = 0; m < 2; m++) {
            const float* W = m ? Wh : Wz;
            for (int i = tid; i < 4096; i += 256) {
                int h2 = i >> 6, h = i & 63;
                sW[m * 64 * WPITCH + h * WPITCH + h2] = W[i];
            }
        }
        if (tid < 64) { sb[tid] = bz[tid]; sb[64 + tid] = bh[tid]; }

        int base = blockIdx.x * 32;
        for (int i = tid; i < 32 * 64; i += 256)
            sx[i] = g_xe[(size_t)base * H + i];
        __syncthreads();

        int h2 = tid & 63, grp = tid >> 6;
        const float* x0 = sx + grp * 8 * 64;
        float az[8] = {0,0,0,0,0,0,0,0}, ah[8] = {0,0,0,0,0,0,0,0};
#pragma unroll 4
        for (int h = 0; h < 64; h++) {
            float wz = sW[h * WPITCH + h2];
            float wh = sW[64 * WPITCH + h * WPITCH + h2];
#pragma unroll
            for (int nb = 0; nb < 8; nb++) {
                float x = x0[nb * 64 + h];
                az[nb] += x * wz; ah[nb] += x * wh;
            }
        }
#pragma unroll
        for (int nb = 0; nb < 8; nb++) {
            int gn = base + grp * 8 + nb;
            float z = sigm(az[nb] + sb[h2]);
            float c = tanhf(ah[nb] + sb[64 + h2]);
            stcg_f1(&g_h[(size_t)gn * H + h2], (1.f - z) * c);   // publishes itself
        }
        __syncthreads();                        // before smem reuse below
    }

    // ================= parent phase (all blocks) =================
    float* sU = sm;                          // 3 * 4096 floats of 2x2-tiled U
    float* sv = sU + 3 * 4096;               // 8 warps * 64

    const float* Us[3] = {Uz, Ur, Uh};
    for (int m = 0; m < 3; m++) {
        const float* U = Us[m];
        for (int i = tid; i < 4096; i += 256) {
            int h2 = i >> 6, h = i & 63;       // coalesced read U[h2][h]
            int dst = m * 4096 + (h >> 1) * 128 + (h2 >> 1) * 4 + ((h & 1) << 1) + (h2 & 1);
            sU[dst] = U[i];
        }
    }
    __syncthreads();

    int gwarp = blockIdx.x * 8 + wid;
    int nwarp = gridDim.x * 8;
    float* svw = sv + wid * 64;
    const float4* sUz4 = (const float4*)(sU);
    const float4* sUr4 = (const float4*)(sU + 4096);
    const float4* sUh4 = (const float4*)(sU + 2 * 4096);

    float2 bz2 = __ldg((const float2*)bz + lane);
    float2 br2 = __ldg((const float2*)br + lane);
    float2 bh2 = __ldg((const float2*)bh + lane);

    float2 mx2 = make_float2(-1e30f, -1e30f);   // per-lane running max (cols 2lane, 2lane+1)

    for (int p = gwarp; p < NP; p += nwarp) {
        const int* tr = tree + (size_t)p * 5;
        int c0 = __ldg(tr + 0), c1 = __ldg(tr + 1), c2 = __ldg(tr + 2), c3 = __ldg(tr + 3);

        // ---- fused A precompute: az/ar/ah = xe@W^T + b ; aq = xe@Wa ----
        float2 xe2 = __ldcg((const float2*)(g_xe + (size_t)(NL + p) * H) + lane);
        float2 az = bz2, ar = br2, ah = bh2, aq = make_float2(0.f, 0.f);
#pragma unroll 8
        for (int h = 0; h < 64; h++) {
            float b = __shfl_sync(FULLM, (h & 1) ? xe2.y : xe2.x, h >> 1);
            float2 wz = __ldg((const float2*)(g_WT            + h * 64) + lane);
            float2 wr = __ldg((const float2*)(g_WT + 1 * 4096 + h * 64) + lane);
            float2 wh = __ldg((const float2*)(g_WT + 2 * 4096 + h * 64) + lane);
            float2 wa = __ldg((const float2*)(g_WT + 3 * 4096 + h * 64) + lane);
            az.x += b * wz.x; az.y += b * wz.y;
            ar.x += b * wr.x; ar.y += b * wr.y;
            ah.x += b * wh.x; ah.y += b * wh.y;
            aq.x += b * wa.x; aq.y += b * wa.y;
        }

        // ---- data-as-flag poll: each lane waits on its own 8B of each child ----
        const void* p0 = (const uint2*)(g_h + (size_t)(c0 < 0 ? 0 : c0) * H) + lane;
        const void* p1 = (const uint2*)(g_h + (size_t)(c1 < 0 ? 0 : c1) * H) + lane;
        const void* p2 = (const uint2*)(g_h + (size_t)(c2 < 0 ? 0 : c2) * H) + lane;
        const void* p3 = (const uint2*)(g_h + (size_t)(c3 < 0 ? 0 : c3) * H) + lane;
        uint2 v0, v1, v2, v3;
        bool r0 = (c0 < 0), r1 = (c1 < 0), r2 = (c2 < 0), r3 = (c3 < 0);
        for (;;) {
            if (!r0) { v0 = ldcg_u2(p0); r0 = (v0.x != MAGIC) && (v0.y != MAGIC); }
            if (!r1) { v1 = ldcg_u2(p1); r1 = (v1.x != MAGIC) && (v1.y != MAGIC); }
            if (!r2) { v2 = ldcg_u2(p2); r2 = (v2.x != MAGIC) && (v2.y != MAGIC); }
            if (!r3) { v3 = ldcg_u2(p3); r3 = (v3.x != MAGIC) && (v3.y != MAGIC); }
            if (r0 && r1 && r2 && r3) break;
            __nanosleep(20);
        }
        float2 ch0 = (c0 >= 0) ? make_float2(__uint_as_float(v0.x), __uint_as_float(v0.y)) : make_float2(0.f, 0.f);
        float2 ch1 = (c1 >= 0) ? make_float2(__uint_as_float(v1.x), __uint_as_float(v1.y)) : make_float2(0.f, 0.f);
        float2 ch2 = (c2 >= 0) ? make_float2(__uint_as_float(v2.x), __uint_as_float(v2.y)) : make_float2(0.f, 0.f);
        float2 ch3 = (c3 >= 0) ? make_float2(__uint_as_float(v3.x), __uint_as_float(v3.y)) : make_float2(0.f, 0.f);

        // attention logits l_j = sigmoid(q . child_j)
        float q0 = aq.x * ch0.x + aq.y * ch0.y;
        float q1 = aq.x * ch1.x + aq.y * ch1.y;
        float q2 = aq.x * ch2.x + aq.y * ch2.y;
        float q3 = aq.x * ch3.x + aq.y * ch3.y;
#pragma unroll
        for (int o = 16; o > 0; o >>= 1) {
            q0 += __shfl_xor_sync(FULLM, q0, o);
            q1 += __shfl_xor_sync(FULLM, q1, o);
            q2 += __shfl_xor_sync(FULLM, q2, o);
            q3 += __shfl_xor_sync(FULLM, q3, o);
        }
        float l0 = (c0 >= 0) ? sigm(q0) : -1e30f;
        float l1 = (c1 >= 0) ? sigm(q1) : -1e30f;
        float l2 = (c2 >= 0) ? sigm(q2) : -1e30f;
        float l3 = (c3 >= 0) ? sigm(q3) : -1e30f;
        float mx = fmaxf(fmaxf(l0, l1), fmaxf(l2, l3));
        float a0 = (c0 >= 0) ? __expf(l0 - mx) : 0.f;
        float a1 = (c1 >= 0) ? __expf(l1 - mx) : 0.f;
        float a2 = (c2 >= 0) ? __expf(l2 - mx) : 0.f;
        float a3 = (c3 >= 0) ? __expf(l3 - mx) : 0.f;
        float inv = 1.f / (a0 + a1 + a2 + a3);
        a0 *= inv; a1 *= inv; a2 *= inv; a3 *= inv;

        float2 ht;
        ht.x = a0 * ch0.x + a1 * ch1.x + a2 * ch2.x + a3 * ch3.x;
        ht.y = a0 * ch0.y + a1 * ch1.y + a2 * ch2.y + a3 * ch3.y;

        ((float2*)svw)[lane] = ht;              // svw[2h']=ht[2h'], pairs readable as float2
        __syncwarp();

        // z/r GEMVs: LDS.128 2x2 tiles, input pairs hp=(2hp,2hp+1)
        float2 accz = make_float2(0.f, 0.f), accr = make_float2(0.f, 0.f);
#pragma unroll 4
        for (int hp = 0; hp < 32; hp++) {
            float2 b2 = ((const float2*)svw)[hp];
            float4 uz = sUz4[hp * 32 + lane];
            float4 ur = sUr4[hp * 32 + lane];
            accz.x += b2.x * uz.x + b2.y * uz.z;
            accz.y += b2.x * uz.y + b2.y * uz.w;
            accr.x += b2.x * ur.x + b2.y * ur.z;
            accr.y += b2.x * ur.y + b2.y * ur.w;
        }
        float2 z = make_float2(sigm(az.x + accz.x), sigm(az.y + accz.y));
        float2 r = make_float2(sigm(ar.x + accr.x), sigm(ar.y + accr.y));

        __syncwarp();
        ((float2*)svw)[lane] = make_float2(r.x * ht.x, r.y * ht.y);
        __syncwarp();

        float2 accc = make_float2(0.f, 0.f);
#pragma unroll 4
        for (int hp = 0; hp < 32; hp++) {
            float2 b2 = ((const float2*)svw)[hp];
            float4 uh = sUh4[hp * 32 + lane];
            accc.x += b2.x * uh.x + b2.y * uh.z;
            accc.y += b2.x * uh.y + b2.y * uh.w;
        }
        float2 cv = make_float2(tanhf(ah.x + accc.x), tanhf(ah.y + accc.y));
        float2 hv;
        hv.x = z.x * ht.x + (1.f - z.x) * cv.x;
        hv.y = z.y * ht.y + (1.f - z.y) * cv.y;
        stcg_f2((float2*)(g_h + (size_t)(NL + p) * H) + lane, hv);   // publishes itself

        mx2.x = fmaxf(mx2.x, hv.x);             // fused row-max over parents
        mx2.y = fmaxf(mx2.y, hv.y);
    }

    // ---- block-level max reduction over this block's parents ----
    __syncwarp();
    ((float2*)svw)[lane] = mx2;                 // sv[wid*64 + col] = lane-pair maxes
    __syncthreads();
    if (tid < 64) {
        float m = sv[tid];
#pragma unroll
        for (int w = 1; w < 8; w++) m = fmaxf(m, sv[w * 64 + tid]);
        g_partial[blockIdx.x * 64 + tid] = m;
    }
}

// ---------------- kernel 4: final max over block partials + logits + softmax ----------------
__global__ void k_final(const float* __restrict__ Wout, const float* __restrict__ bout,
                        float* __restrict__ out, int npart) {
    __shared__ float sred[4][64];
    __shared__ float fm[64];
    __shared__ float lg[4];
    int tid = threadIdx.x;               // 256
    int col = tid & 63, g = tid >> 6;
    float m = -1e30f;
    for (int b = g; b < npart; b += 4)
        m = fmaxf(m, g_partial[b * 64 + col]);
    sred[g][col] = m;
    __syncthreads();
    if (tid < 64)
        fm[tid] = fmaxf(fmaxf(sred[0][tid], sred[1][tid]),
                        fmaxf(sred[2][tid], sred[3][tid]));
    __syncthreads();
    if (tid < NCLASS) {
        float s = bout[tid];
        for (int h = 0; h < 64; h++) s += Wout[tid * 64 + h] * fm[h];
        lg[tid] = s;
    }
    __syncthreads();
    if (tid == 0) {
        float mx = fmaxf(fmaxf(lg[0], lg[1]), fmaxf(lg[2], lg[3]));
        float e0 = __expf(lg[0] - mx), e1 = __expf(lg[1] - mx);
        float e2 = __expf(lg[2] - mx), e3 = __expf(lg[3] - mx);
        float s = e0 + e1 + e2 + e3;
        out[0] = e0 / s; out[1] = e1 / s; out[2] = e2 / s; out[3] = e3 / s;
    }
}

// ---------------- launch ----------------
extern "C" void kernel_launch(void* const* d_in, const int* in_sizes, int n_in,
                              void* d_out, int out_size) {
    const float* x_word  = (const float*)d_in[0];
    const int*   x_index = (const int*)  d_in[1];
    const int*   tree    = (const int*)  d_in[2];
    const float* E       = (const float*)d_in[3];
    const float* Wz      = (const float*)d_in[4];
    const float* Uz      = (const float*)d_in[5];
    const float* bz      = (const float*)d_in[6];
    const float* Wr      = (const float*)d_in[7];
    const float* Ur      = (const float*)d_in[8];
    const float* br      = (const float*)d_in[9];
    const float* Wh      = (const float*)d_in[10];
    const float* Uh      = (const float*)d_in[11];
    const float* bh      = (const float*)d_in[12];
    const float* Wa      = (const float*)d_in[13];
    const float* Wout    = (const float*)d_in[14];
    const float* bout    = (const float*)d_in[15];
    float* out = (float*)d_out;

    const int smemMain = (3 * 4096 + 8 * 64) * 4;                   // 51200 B
    cudaFuncSetAttribute(k_main, cudaFuncAttributeMaxDynamicSharedMemorySize, smemMain);

    int dev = 0;
    cudaGetDevice(&dev);
    int sms = 0;
    if (cudaDeviceGetAttribute(&sms, cudaDevAttrMultiProcessorCount, dev) != cudaSuccess || sms <= 0)
        sms = 148;
    int nb = 0;
    if (cudaOccupancyMaxActiveBlocksPerMultiprocessor(&nb, k_main, 256, smemMain) != cudaSuccess || nb < 1)
        nb = 1;
    int pgrid = sms * nb;                  // guaranteed co-resident
    if (pgrid > NP / 8) pgrid = NP / 8;
    if (pgrid < LEAFB) pgrid = LEAFB;      // all leaf tiles must be covered
    if (pgrid > 1024) pgrid = 1024;        // g_partial capacity
    if (pgrid < 1) pgrid = 1;

    k_prep<<<4 + (NN * H / 4 + 255) / 256, 256>>>(Wz, Wr, Wh, Wa);
    k_transpose<<<3125, 256>>>(E);
    k_embed<<<2048, 256>>>(x_word, x_index);
    k_main<<<pgrid, 256, smemMain>>>(Uz, Ur, Uh, tree, Wz, Wh, bz, br, bh);
    k_final<<<1, 256>>>(Wout, bout, out, pgrid);
}

// round 12
// speedup vs baseline: 1.4807x; 1.0974x over previous
#include <cuda_runtime.h>
#include <cstdint>

#define NN      16384      // N_NODES
#define NP      8192       // N_PARENTS
#define NL      8192       // leaves
#define KW      32
#define H       64
#define VOCAB   100000
#define NCLASS  4

#define WPITCH  65         // smem pitch for scalar-read weight tiles (conflict-free)
#define UPITCH  66         // smem pitch for float2-read U tiles (even, conflict-free)
#define LEAFB   256        // leaf-phase blocks (32 leaves each)
#define FULLM   0xffffffffu
#define MAGIC   0x7f800001u   // sNaN bit pattern: impossible as a finite GRU output

// ---------------- device scratch (no allocations allowed) ----------------
__device__ __align__(16) float g_ET[(size_t)VOCAB * H];   // 25.6 MB  E transposed
__device__ __align__(16) float g_xe[(size_t)NN * H];      // 4 MB     xe
__device__ __align__(16) float g_h [(size_t)NN * H];      // 4 MB     node_h (sentinel-init)
__device__ __align__(16) float g_WT[4 * H * H];           // 64 KB    Wz^T,Wr^T,Wh^T,Wa (in,out)
__device__ float g_partial[1024 * H];                     // per-block max partials

__device__ __forceinline__ float sigm(float x) { return 1.f / (1.f + __expf(-x)); }

// poll load: L2-coherent, never hoisted
__device__ __forceinline__ uint2 ldcg_u2(const void* p) {
    uint2 v;
    asm volatile("ld.global.cg.v2.u32 {%0,%1}, [%2];"
                 : "=r"(v.x), "=r"(v.y) : "l"(p) : "memory");
    return v;
}
__device__ __forceinline__ void stcg_f2(void* p, float2 v) {
    asm volatile("st.global.cg.v2.f32 [%0], {%1,%2};"
                 :: "l"(p), "f"(v.x), "f"(v.y) : "memory");
}
__device__ __forceinline__ void stcg_f1(void* p, float v) {
    asm volatile("st.global.cg.f32 [%0], %1;" :: "l"(p), "f"(v) : "memory");
}

// ---------------- kernel 0: build WT + sentinel-init g_h ----------------
// Wz/Wr/Wh stored transposed WT[h][h2]=W[h2][h] (xe @ W^T); Wa stored DIRECT (xe @ Wa).
__global__ void k_prep(const float* __restrict__ Wz, const float* __restrict__ Wr,
                       const float* __restrict__ Wh, const float* __restrict__ Wa) {
    if (blockIdx.x < 3) {
        __shared__ float t[64][65];
        const float* W = (blockIdx.x == 0) ? Wz : (blockIdx.x == 1) ? Wr : Wh;
        int tid = threadIdx.x;
        for (int i = tid; i < 4096; i += 256) {
            int r = i >> 6, c = i & 63;
            t[r][c] = W[i];
        }
        __syncthreads();
        float* WT = g_WT + blockIdx.x * 4096;
        for (int i = tid; i < 4096; i += 256) {
            int h = i >> 6, h2 = i & 63;
            WT[i] = t[h2][h];
        }
    } else if (blockIdx.x == 3) {
        int tid = threadIdx.x;
        float* WT = g_WT + 3 * 4096;
        for (int i = tid; i < 4096; i += 256)
            WT[i] = Wa[i];
    } else {
        // sentinel-init g_h: 16384*64 floats = 262144 uint4
        int i = (blockIdx.x - 4) * 256 + threadIdx.x;
        if (i < (NN * H / 4))
            ((uint4*)g_h)[i] = make_uint4(MAGIC, MAGIC, MAGIC, MAGIC);
    }
}

// ---------------- kernel 1: transpose E (H, VOCAB) -> (VOCAB, H) ----------------
__global__ void k_transpose(const float* __restrict__ E) {
    __shared__ float sm[64][33];
    int v0 = blockIdx.x * 32;
    int tid = threadIdx.x;
    int vv = tid & 31, hh = tid >> 5;
#pragma unroll
    for (int h0 = 0; h0 < 64; h0 += 8)
        sm[h0 + hh][vv] = E[(size_t)(h0 + hh) * VOCAB + v0 + vv];
    __syncthreads();
#pragma unroll
    for (int i = tid; i < 2048; i += 256) {
        int v = i >> 6, h = i & 63;
        g_ET[(size_t)(v0 + v) * H + h] = sm[h][v];
    }
}

// ---------------- kernel 2: xe[n,h] = sum_k x_word[n,k] * E_T[idx[n,k], h] ----------------
__global__ void __launch_bounds__(256) k_embed(const float* __restrict__ xw,
                                               const int* __restrict__ xi) {
    int warp = (blockIdx.x * blockDim.x + threadIdx.x) >> 5;
    int lane = threadIdx.x & 31;
    if (warp >= NN) return;
    float w  = xw[warp * KW + lane];
    int   ix = xi[warp * KW + lane];
    float2 acc = make_float2(0.f, 0.f);
#pragma unroll 4
    for (int j = 0; j < 32; j++) {
        int   idx = __shfl_sync(FULLM, ix, j);
        float wj  = __shfl_sync(FULLM, w,  j);
        float2 e = *(const float2*)(&g_ET[(size_t)idx * H + 2 * lane]);
        acc.x += wj * e.x;
        acc.y += wj * e.y;
    }
    *(float2*)(&g_xe[(size_t)warp * H + 2 * lane]) = acc;
}

// ---------------- kernel 3: persistent main (leaf phase + parent GRU + fused max) ----------------
// Exact R9 body; ONLY delta: per-warp running max of produced parent rows, block-reduced
// at the end into g_partial (replaces the separate 6.6us k_rmax launch).
__global__ void __launch_bounds__(256, 4) k_main(const float* __restrict__ Uz,
                                                 const float* __restrict__ Ur,
                                                 const float* __restrict__ Uh,
                                                 const int*   __restrict__ tree,
                                                 const float* __restrict__ Wz,
                                                 const float* __restrict__ Wh,
                                                 const float* __restrict__ bz,
                                                 const float* __restrict__ br,
                                                 const float* __restrict__ bh) {
    extern __shared__ float sm[];
    int tid = threadIdx.x;
    int wid = tid >> 5, lane = tid & 31;

    // ================= leaf phase (blocks 0..LEAFB-1) =================
    if (blockIdx.x < LEAFB) {
        float* sW = sm;                         // 2 * 64 * WPITCH
        float* sb = sW + 2 * 64 * WPITCH;       // 2 * 64
        float* sx = sb + 2 * 64;                // 32 * 64

        for (int m = 0; m < 2; m++) {
            const float* W = m ? Wh : Wz;
            for (int i = tid; i < 4096; i += 256) {
                int h2 = i >> 6, h = i & 63;
                sW[m * 64 * WPITCH + h * WPITCH + h2] = W[i];
            }
        }
        if (tid < 64) { sb[tid] = bz[tid]; sb[64 + tid] = bh[tid]; }

        int base = blockIdx.x * 32;
        for (int i = tid; i < 32 * 64; i += 256)
            sx[i] = g_xe[(size_t)base * H + i];
        __syncthreads();

        int h2 = tid & 63, grp = tid >> 6;
        const float* x0 = sx + grp * 8 * 64;
        float az[8] = {0,0,0,0,0,0,0,0}, ah[8] = {0,0,0,0,0,0,0,0};
#pragma unroll 4
        for (int h = 0; h < 64; h++) {
            float wz = sW[h * WPITCH + h2];
            float wh = sW[64 * WPITCH + h * WPITCH + h2];
#pragma unroll
            for (int nb = 0; nb < 8; nb++) {
                float x = x0[nb * 64 + h];
                az[nb] += x * wz; ah[nb] += x * wh;
            }
        }
#pragma unroll
        for (int nb = 0; nb < 8; nb++) {
            int gn = base + grp * 8 + nb;
            float z = sigm(az[nb] + sb[h2]);
            float c = tanhf(ah[nb] + sb[64 + h2]);
            stcg_f1(&g_h[(size_t)gn * H + h2], (1.f - z) * c);   // publishes itself
        }
        __syncthreads();                        // before smem reuse below
    }

    // ================= parent phase (all blocks) =================
    float* sU = sm;                          // 3 * 64 * UPITCH, input-major (U^T)
    float* sv = sU + 3 * 64 * UPITCH;        // 8 warps * 64

    const float* Us[3] = {Uz, Ur, Uh};
    for (int m = 0; m < 3; m++) {
        const float* U = Us[m];
        for (int i = tid; i < 4096; i += 256) {
            int h2 = i >> 6, h = i & 63;
            sU[m * 64 * UPITCH + h * UPITCH + h2] = U[i];
        }
    }
    __syncthreads();

    int gwarp = blockIdx.x * 8 + wid;
    int nwarp = gridDim.x * 8;
    float* svw = sv + wid * 64;
    const float* sUz = sU;
    const float* sUr = sU + 64 * UPITCH;
    const float* sUh = sU + 2 * 64 * UPITCH;

    float2 bz2 = __ldg((const float2*)bz + lane);
    float2 br2 = __ldg((const float2*)br + lane);
    float2 bh2 = __ldg((const float2*)bh + lane);

    float2 mx2 = make_float2(-1e30f, -1e30f);   // running max of produced parent rows

    for (int p = gwarp; p < NP; p += nwarp) {
        const int* tr = tree + (size_t)p * 5;
        int c0 = __ldg(tr + 0), c1 = __ldg(tr + 1), c2 = __ldg(tr + 2), c3 = __ldg(tr + 3);

        // ---- fused A precompute: az/ar/ah = xe@W^T + b ; aq = xe@Wa ----
        float2 xe2 = __ldcg((const float2*)(g_xe + (size_t)(NL + p) * H) + lane);
        float2 az = bz2, ar = br2, ah = bh2, aq = make_float2(0.f, 0.f);
#pragma unroll 8
        for (int h = 0; h < 64; h++) {
            float b = __shfl_sync(FULLM, (h & 1) ? xe2.y : xe2.x, h >> 1);
            float2 wz = __ldg((const float2*)(g_WT            + h * 64) + lane);
            float2 wr = __ldg((const float2*)(g_WT + 1 * 4096 + h * 64) + lane);
            float2 wh = __ldg((const float2*)(g_WT + 2 * 4096 + h * 64) + lane);
            float2 wa = __ldg((const float2*)(g_WT + 3 * 4096 + h * 64) + lane);
            az.x += b * wz.x; az.y += b * wz.y;
            ar.x += b * wr.x; ar.y += b * wr.y;
            ah.x += b * wh.x; ah.y += b * wh.y;
            aq.x += b * wa.x; aq.y += b * wa.y;
        }

        // ---- data-as-flag poll: each lane waits on its own 8B of each child ----
        const void* p0 = (const uint2*)(g_h + (size_t)(c0 < 0 ? 0 : c0) * H) + lane;
        const void* p1 = (const uint2*)(g_h + (size_t)(c1 < 0 ? 0 : c1) * H) + lane;
        const void* p2 = (const uint2*)(g_h + (size_t)(c2 < 0 ? 0 : c2) * H) + lane;
        const void* p3 = (const uint2*)(g_h + (size_t)(c3 < 0 ? 0 : c3) * H) + lane;
        uint2 v0, v1, v2, v3;
        bool r0 = (c0 < 0), r1 = (c1 < 0), r2 = (c2 < 0), r3 = (c3 < 0);
        for (;;) {
            if (!r0) { v0 = ldcg_u2(p0); r0 = (v0.x != MAGIC) && (v0.y != MAGIC); }
            if (!r1) { v1 = ldcg_u2(p1); r1 = (v1.x != MAGIC) && (v1.y != MAGIC); }
            if (!r2) { v2 = ldcg_u2(p2); r2 = (v2.x != MAGIC) && (v2.y != MAGIC); }
            if (!r3) { v3 = ldcg_u2(p3); r3 = (v3.x != MAGIC) && (v3.y != MAGIC); }
            if (r0 && r1 && r2 && r3) break;
            __nanosleep(20);
        }
        float2 ch0 = (c0 >= 0) ? make_float2(__uint_as_float(v0.x), __uint_as_float(v0.y)) : make_float2(0.f, 0.f);
        float2 ch1 = (c1 >= 0) ? make_float2(__uint_as_float(v1.x), __uint_as_float(v1.y)) : make_float2(0.f, 0.f);
        float2 ch2 = (c2 >= 0) ? make_float2(__uint_as_float(v2.x), __uint_as_float(v2.y)) : make_float2(0.f, 0.f);
        float2 ch3 = (c3 >= 0) ? make_float2(__uint_as_float(v3.x), __uint_as_float(v3.y)) : make_float2(0.f, 0.f);

        // attention logits l_j = sigmoid(q . child_j)
        float q0 = aq.x * ch0.x + aq.y * ch0.y;
        float q1 = aq.x * ch1.x + aq.y * ch1.y;
        float q2 = aq.x * ch2.x + aq.y * ch2.y;
        float q3 = aq.x * ch3.x + aq.y * ch3.y;
#pragma unroll
        for (int o = 16; o > 0; o >>= 1) {
            q0 += __shfl_xor_sync(FULLM, q0, o);
            q1 += __shfl_xor_sync(FULLM, q1, o);
            q2 += __shfl_xor_sync(FULLM, q2, o);
            q3 += __shfl_xor_sync(FULLM, q3, o);
        }
        float l0 = (c0 >= 0) ? sigm(q0) : -1e30f;
        float l1 = (c1 >= 0) ? sigm(q1) : -1e30f;
        float l2 = (c2 >= 0) ? sigm(q2) : -1e30f;
        float l3 = (c3 >= 0) ? sigm(q3) : -1e30f;
        float mx = fmaxf(fmaxf(l0, l1), fmaxf(l2, l3));
        float a0 = (c0 >= 0) ? __expf(l0 - mx) : 0.f;
        float a1 = (c1 >= 0) ? __expf(l1 - mx) : 0.f;
        float a2 = (c2 >= 0) ? __expf(l2 - mx) : 0.f;
        float a3 = (c3 >= 0) ? __expf(l3 - mx) : 0.f;
        float inv = 1.f / (a0 + a1 + a2 + a3);
        a0 *= inv; a1 *= inv; a2 *= inv; a3 *= inv;

        float2 ht;
        ht.x = a0 * ch0.x + a1 * ch1.x + a2 * ch2.x + a3 * ch3.x;
        ht.y = a0 * ch0.y + a1 * ch1.y + a2 * ch2.y + a3 * ch3.y;

        ((float2*)svw)[lane] = ht;
        __syncwarp();

        // z/r GEMVs: two 32-deep accumulator chains
        float2 accz0 = make_float2(0.f, 0.f), accz1 = make_float2(0.f, 0.f);
        float2 accr0 = make_float2(0.f, 0.f), accr1 = make_float2(0.f, 0.f);
#pragma unroll 4
        for (int hp = 0; hp < 32; hp++) {
            float  b0  = svw[hp];
            float  b1  = svw[hp + 32];
            float2 uzA = *(const float2*)(sUz + hp        * UPITCH + 2 * lane);
            float2 uzB = *(const float2*)(sUz + (hp + 32) * UPITCH + 2 * lane);
            float2 urA = *(const float2*)(sUr + hp        * UPITCH + 2 * lane);
            float2 urB = *(const float2*)(sUr + (hp + 32) * UPITCH + 2 * lane);
            accz0.x += b0 * uzA.x; accz0.y += b0 * uzA.y;
            accz1.x += b1 * uzB.x; accz1.y += b1 * uzB.y;
            accr0.x += b0 * urA.x; accr0.y += b0 * urA.y;
            accr1.x += b1 * urB.x; accr1.y += b1 * urB.y;
        }
        float2 z = make_float2(sigm(az.x + accz0.x + accz1.x), sigm(az.y + accz0.y + accz1.y));
        float2 r = make_float2(sigm(ar.x + accr0.x + accr1.x), sigm(ar.y + accr0.y + accr1.y));

        __syncwarp();
        ((float2*)svw)[lane] = make_float2(r.x * ht.x, r.y * ht.y);
        __syncwarp();

        float2 accc0 = make_float2(0.f, 0.f), accc1 = make_float2(0.f, 0.f);
#pragma unroll 4
        for (int hp = 0; hp < 32; hp++) {
            float  b0  = svw[hp];
            float  b1  = svw[hp + 32];
            float2 uhA = *(const float2*)(sUh + hp        * UPITCH + 2 * lane);
            float2 uhB = *(const float2*)(sUh + (hp + 32) * UPITCH + 2 * lane);
            accc0.x += b0 * uhA.x; accc0.y += b0 * uhA.y;
            accc1.x += b1 * uhB.x; accc1.y += b1 * uhB.y;
        }
        float2 cv = make_float2(tanhf(ah.x + accc0.x + accc1.x), tanhf(ah.y + accc0.y + accc1.y));
        float2 hv;
        hv.x = z.x * ht.x + (1.f - z.x) * cv.x;
        hv.y = z.y * ht.y + (1.f - z.y) * cv.y;
        stcg_f2((float2*)(g_h + (size_t)(NL + p) * H) + lane, hv);   // publishes itself

        mx2.x = fmaxf(mx2.x, hv.x);             // fused row-max over produced parents
        mx2.y = fmaxf(mx2.y, hv.y);
    }

    // ---- block-level max reduction over this block's produced parents ----
    __syncwarp();
    ((float2*)svw)[lane] = mx2;
    __syncthreads();
    if (tid < 64) {
        float m = sv[tid];
#pragma unroll
        for (int w = 1; w < 8; w++) m = fmaxf(m, sv[w * 64 + tid]);
        g_partial[blockIdx.x * 64 + tid] = m;
    }
}

// ---------------- kernel 4: final max over block partials + logits + softmax ----------------
__global__ void k_final(const float* __restrict__ Wout, const float* __restrict__ bout,
                        float* __restrict__ out, int npart) {
    __shared__ float sred[4][64];
    __shared__ float fm[64];
    __shared__ float lg[4];
    int tid = threadIdx.x;               // 256
    int col = tid & 63, g = tid >> 6;
    float m = -1e30f;
    for (int b = g; b < npart; b += 4)
        m = fmaxf(m, g_partial[b * 64 + col]);
    sred[g][col] = m;
    __syncthreads();
    if (tid < 64)
        fm[tid] = fmaxf(fmaxf(sred[0][tid], sred[1][tid]),
                        fmaxf(sred[2][tid], sred[3][tid]));
    __syncthreads();
    if (tid < NCLASS) {
        float s = bout[tid];
        for (int h = 0; h < 64; h++) s += Wout[tid * 64 + h] * fm[h];
        lg[tid] = s;
    }
    __syncthreads();
    if (tid == 0) {
        float mx = fmaxf(fmaxf(lg[0], lg[1]), fmaxf(lg[2], lg[3]));
        float e0 = __expf(lg[0] - mx), e1 = __expf(lg[1] - mx);
        float e2 = __expf(lg[2] - mx), e3 = __expf(lg[3] - mx);
        float s = e0 + e1 + e2 + e3;
        out[0] = e0 / s; out[1] = e1 / s; out[2] = e2 / s; out[3] = e3 / s;
    }
}

// ---------------- launch ----------------
extern "C" void kernel_launch(void* const* d_in, const int* in_sizes, int n_in,
                              void* d_out, int out_size) {
    const float* x_word  = (const float*)d_in[0];
    const int*   x_index = (const int*)  d_in[1];
    const int*   tree    = (const int*)  d_in[2];
    const float* E       = (const float*)d_in[3];
    const float* Wz      = (const float*)d_in[4];
    const float* Uz      = (const float*)d_in[5];
    const float* bz      = (const float*)d_in[6];
    const float* Wr      = (const float*)d_in[7];
    const float* Ur      = (const float*)d_in[8];
    const float* br      = (const float*)d_in[9];
    const float* Wh      = (const float*)d_in[10];
    const float* Uh      = (const float*)d_in[11];
    const float* bh      = (const float*)d_in[12];
    const float* Wa      = (const float*)d_in[13];
    const float* Wout    = (const float*)d_in[14];
    const float* bout    = (const float*)d_in[15];
    float* out = (float*)d_out;

    const int smemMain = (3 * 64 * UPITCH + 8 * 64) * 4;            // 52736 B
    cudaFuncSetAttribute(k_main, cudaFuncAttributeMaxDynamicSharedMemorySize, smemMain);

    int dev = 0;
    cudaGetDevice(&dev);
    int sms = 0;
    if (cudaDeviceGetAttribute(&sms, cudaDevAttrMultiProcessorCount, dev) != cudaSuccess || sms <= 0)
        sms = 148;
    int nb = 0;
    if (cudaOccupancyMaxActiveBlocksPerMultiprocessor(&nb, k_main, 256, smemMain) != cudaSuccess || nb < 1)
        nb = 1;
    int pgrid = sms * nb;                  // guaranteed co-resident
    if (pgrid > NP / 8) pgrid = NP / 8;
    if (pgrid < LEAFB) pgrid = LEAFB;      // all leaf tiles must be covered
    if (pgrid > 1024) pgrid = 1024;        // g_partial capacity
    if (pgrid < 1) pgrid = 1;

    k_prep<<<4 + (NN * H / 4 + 255) / 256, 256>>>(Wz, Wr, Wh, Wa);
    k_transpose<<<3125, 256>>>(E);
    k_embed<<<2048, 256>>>(x_word, x_index);
    k_main<<<pgrid, 256, smemMain>>>(Uz, Ur, Uh, tree, Wz, Wh, bz, br, bh);
    k_final<<<1, 256>>>(Wout, bout, out, pgrid);
}

// round 13
// speedup vs baseline: 1.6678x; 1.1263x over previous
#include <cuda_runtime.h>
#include <cstdint>

#define NN      16384      // N_NODES
#define NP      8192       // N_PARENTS
#define NL      8192       // leaves
#define KW      32
#define H       64
#define VOCAB   100000
#define NCLASS  4

#define UPITCH  66         // smem pitch for float2-read U tiles (even, conflict-free)
#define FULLM   0xffffffffu
#define MAGIC   0x7f800001u   // sNaN bit pattern: impossible as a finite GRU output

// ---------------- device scratch (no allocations allowed) ----------------
__device__ __align__(16) float g_ET[(size_t)VOCAB * H];   // 25.6 MB  E transposed
__device__ __align__(16) float g_xe[(size_t)NN * H];      // 4 MB     xe
__device__ __align__(16) float g_h [(size_t)NN * H];      // 4 MB     node_h (sentinel-init)
__device__ __align__(16) float g_WT[4 * H * H];           // 64 KB    Wz^T,Wr^T,Wh^T,Wa (in,out)
__device__ float g_partial[256 * H];                      // rmax partials

__device__ __forceinline__ float sigm(float x) { return 1.f / (1.f + __expf(-x)); }

// poll load: L2-coherent, never hoisted
__device__ __forceinline__ uint2 ldcg_u2(const void* p) {
    uint2 v;
    asm volatile("ld.global.cg.v2.u32 {%0,%1}, [%2];"
                 : "=r"(v.x), "=r"(v.y) : "l"(p) : "memory");
    return v;
}
__device__ __forceinline__ void stcg_f2(void* p, float2 v) {
    asm volatile("st.global.cg.v2.f32 [%0], {%1,%2};"
                 :: "l"(p), "f"(v.x), "f"(v.y) : "memory");
}

// ---------------- kernel 0: build WT + sentinel-init g_h ----------------
// Wz/Wr/Wh stored transposed WT[h][h2]=W[h2][h] (xe @ W^T); Wa stored DIRECT (xe @ Wa).
__global__ void k_prep(const float* __restrict__ Wz, const float* __restrict__ Wr,
                       const float* __restrict__ Wh, const float* __restrict__ Wa) {
    if (blockIdx.x < 3) {
        __shared__ float t[64][65];
        const float* W = (blockIdx.x == 0) ? Wz : (blockIdx.x == 1) ? Wr : Wh;
        int tid = threadIdx.x;
        for (int i = tid; i < 4096; i += 256) {
            int r = i >> 6, c = i & 63;
            t[r][c] = W[i];
        }
        __syncthreads();
        float* WT = g_WT + blockIdx.x * 4096;
        for (int i = tid; i < 4096; i += 256) {
            int h = i >> 6, h2 = i & 63;
            WT[i] = t[h2][h];
        }
    } else if (blockIdx.x == 3) {
        int tid = threadIdx.x;
        float* WT = g_WT + 3 * 4096;
        for (int i = tid; i < 4096; i += 256)
            WT[i] = Wa[i];
    } else {
        // sentinel-init g_h: 16384*64 floats = 262144 uint4
        int i = (blockIdx.x - 4) * 256 + threadIdx.x;
        if (i < (NN * H / 4))
            ((uint4*)g_h)[i] = make_uint4(MAGIC, MAGIC, MAGIC, MAGIC);
    }
}

// ---------------- kernel 1: transpose E (H, VOCAB) -> (VOCAB, H) ----------------
__global__ void k_transpose(const float* __restrict__ E) {
    __shared__ float sm[64][33];
    int v0 = blockIdx.x * 32;
    int tid = threadIdx.x;
    int vv = tid & 31, hh = tid >> 5;
#pragma unroll
    for (int h0 = 0; h0 < 64; h0 += 8)
        sm[h0 + hh][vv] = E[(size_t)(h0 + hh) * VOCAB + v0 + vv];
    __syncthreads();
#pragma unroll
    for (int i = tid; i < 2048; i += 256) {
        int v = i >> 6, h = i & 63;
        g_ET[(size_t)(v0 + v) * H + h] = sm[h][v];
    }
}

// ---------------- kernel 2: xe[n,h] = sum_k x_word[n,k] * E_T[idx[n,k], h] ----------------
__global__ void __launch_bounds__(256) k_embed(const float* __restrict__ xw,
                                               const int* __restrict__ xi) {
    int warp = (blockIdx.x * blockDim.x + threadIdx.x) >> 5;
    int lane = threadIdx.x & 31;
    if (warp >= NN) return;
    float w  = xw[warp * KW + lane];
    int   ix = xi[warp * KW + lane];
    float2 acc = make_float2(0.f, 0.f);
#pragma unroll 4
    for (int j = 0; j < 32; j++) {
        int   idx = __shfl_sync(FULLM, ix, j);
        float wj  = __shfl_sync(FULLM, w,  j);
        float2 e = *(const float2*)(&g_ET[(size_t)idx * H + 2 * lane]);
        acc.x += wj * e.x;
        acc.y += wj * e.y;
    }
    *(float2*)(&g_xe[(size_t)warp * H + 2 * lane]) = acc;
}

// ---------------- kernel 3: persistent main (warp-per-leaf + parent GRU) ----------------
// Sync is data-as-flag on g_h. Leaves: each warp computes its ~2 leaves via L1-resident
// g_WT (same pattern as the parent A-precompute) and publishes immediately — no block
// tiling, no smem phase juggling. Parent phase is byte-identical to R9 (74.7us measured).
// Deadlock-free: leaf loop terminates unconditionally; parent deps point to strictly
// smaller node indices; full grid co-resident (occupancy-sized).
__global__ void __launch_bounds__(256, 4) k_main(const float* __restrict__ Uz,
                                                 const float* __restrict__ Ur,
                                                 const float* __restrict__ Uh,
                                                 const int*   __restrict__ tree,
                                                 const float* __restrict__ bz,
                                                 const float* __restrict__ br,
                                                 const float* __restrict__ bh) {
    extern __shared__ float sm[];
    float* sU = sm;                          // 3 * 64 * UPITCH, input-major (U^T)
    float* sv = sU + 3 * 64 * UPITCH;        // 8 warps * 64
    int tid = threadIdx.x;

    const float* Us[3] = {Uz, Ur, Uh};
    for (int m = 0; m < 3; m++) {
        const float* U = Us[m];
        for (int i = tid; i < 4096; i += 256) {
            int h2 = i >> 6, h = i & 63;
            sU[m * 64 * UPITCH + h * UPITCH + h2] = U[i];
        }
    }
    __syncthreads();

    int wid = tid >> 5, lane = tid & 31;
    int gwarp = blockIdx.x * 8 + wid;
    int nwarp = gridDim.x * 8;
    float* svw = sv + wid * 64;
    const float* sUz = sU;
    const float* sUr = sU + 64 * UPITCH;
    const float* sUh = sU + 2 * 64 * UPITCH;

    float2 bz2 = __ldg((const float2*)bz + lane);
    float2 br2 = __ldg((const float2*)br + lane);
    float2 bh2 = __ldg((const float2*)bh + lane);

    // ---------- leaf loop: warp-per-leaf, WT-based, publishes via sentinel-clear ----------
    for (int t = gwarp; t < NL; t += nwarp) {
        float2 xe2 = __ldcg((const float2*)(g_xe + (size_t)t * H) + lane);
        float2 az = bz2, ah = bh2;
#pragma unroll 8
        for (int h = 0; h < 64; h++) {
            float b = __shfl_sync(FULLM, (h & 1) ? xe2.y : xe2.x, h >> 1);
            float2 wz = __ldg((const float2*)(g_WT            + h * 64) + lane);
            float2 wh = __ldg((const float2*)(g_WT + 2 * 4096 + h * 64) + lane);
            az.x += b * wz.x; az.y += b * wz.y;
            ah.x += b * wh.x; ah.y += b * wh.y;
        }
        float2 hv;
        hv.x = (1.f - sigm(az.x)) * tanhf(ah.x);
        hv.y = (1.f - sigm(az.y)) * tanhf(ah.y);
        stcg_f2((float2*)(g_h + (size_t)t * H) + lane, hv);   // publishes itself
    }

    // ---------- parent loop: byte-identical to R9 ----------
    for (int p = gwarp; p < NP; p += nwarp) {
        const int* tr = tree + (size_t)p * 5;
        int c0 = __ldg(tr + 0), c1 = __ldg(tr + 1), c2 = __ldg(tr + 2), c3 = __ldg(tr + 3);

        // ---- fused A precompute: az/ar/ah = xe@W^T + b ; aq = xe@Wa ----
        float2 xe2 = __ldcg((const float2*)(g_xe + (size_t)(NL + p) * H) + lane);
        float2 az = bz2, ar = br2, ah = bh2, aq = make_float2(0.f, 0.f);
#pragma unroll 8
        for (int h = 0; h < 64; h++) {
            float b = __shfl_sync(FULLM, (h & 1) ? xe2.y : xe2.x, h >> 1);
            float2 wz = __ldg((const float2*)(g_WT            + h * 64) + lane);
            float2 wr = __ldg((const float2*)(g_WT + 1 * 4096 + h * 64) + lane);
            float2 wh = __ldg((const float2*)(g_WT + 2 * 4096 + h * 64) + lane);
            float2 wa = __ldg((const float2*)(g_WT + 3 * 4096 + h * 64) + lane);
            az.x += b * wz.x; az.y += b * wz.y;
            ar.x += b * wr.x; ar.y += b * wr.y;
            ah.x += b * wh.x; ah.y += b * wh.y;
            aq.x += b * wa.x; aq.y += b * wa.y;
        }

        // ---- data-as-flag poll: each lane waits on its own 8B of each child ----
        const void* p0 = (const uint2*)(g_h + (size_t)(c0 < 0 ? 0 : c0) * H) + lane;
        const void* p1 = (const uint2*)(g_h + (size_t)(c1 < 0 ? 0 : c1) * H) + lane;
        const void* p2 = (const uint2*)(g_h + (size_t)(c2 < 0 ? 0 : c2) * H) + lane;
        const void* p3 = (const uint2*)(g_h + (size_t)(c3 < 0 ? 0 : c3) * H) + lane;
        uint2 v0, v1, v2, v3;
        bool r0 = (c0 < 0), r1 = (c1 < 0), r2 = (c2 < 0), r3 = (c3 < 0);
        for (;;) {
            if (!r0) { v0 = ldcg_u2(p0); r0 = (v0.x != MAGIC) && (v0.y != MAGIC); }
            if (!r1) { v1 = ldcg_u2(p1); r1 = (v1.x != MAGIC) && (v1.y != MAGIC); }
            if (!r2) { v2 = ldcg_u2(p2); r2 = (v2.x != MAGIC) && (v2.y != MAGIC); }
            if (!r3) { v3 = ldcg_u2(p3); r3 = (v3.x != MAGIC) && (v3.y != MAGIC); }
            if (r0 && r1 && r2 && r3) break;
            __nanosleep(20);
        }
        float2 ch0 = (c0 >= 0) ? make_float2(__uint_as_float(v0.x), __uint_as_float(v0.y)) : make_float2(0.f, 0.f);
        float2 ch1 = (c1 >= 0) ? make_float2(__uint_as_float(v1.x), __uint_as_float(v1.y)) : make_float2(0.f, 0.f);
        float2 ch2 = (c2 >= 0) ? make_float2(__uint_as_float(v2.x), __uint_as_float(v2.y)) : make_float2(0.f, 0.f);
        float2 ch3 = (c3 >= 0) ? make_float2(__uint_as_float(v3.x), __uint_as_float(v3.y)) : make_float2(0.f, 0.f);

        // attention logits l_j = sigmoid(q . child_j)
        float q0 = aq.x * ch0.x + aq.y * ch0.y;
        float q1 = aq.x * ch1.x + aq.y * ch1.y;
        float q2 = aq.x * ch2.x + aq.y * ch2.y;
        float q3 = aq.x * ch3.x + aq.y * ch3.y;
#pragma unroll
        for (int o = 16; o > 0; o >>= 1) {
            q0 += __shfl_xor_sync(FULLM, q0, o);
            q1 += __shfl_xor_sync(FULLM, q1, o);
            q2 += __shfl_xor_sync(FULLM, q2, o);
            q3 += __shfl_xor_sync(FULLM, q3, o);
        }
        float l0 = (c0 >= 0) ? sigm(q0) : -1e30f;
        float l1 = (c1 >= 0) ? sigm(q1) : -1e30f;
        float l2 = (c2 >= 0) ? sigm(q2) : -1e30f;
        float l3 = (c3 >= 0) ? sigm(q3) : -1e30f;
        float mx = fmaxf(fmaxf(l0, l1), fmaxf(l2, l3));
        float a0 = (c0 >= 0) ? __expf(l0 - mx) : 0.f;
        float a1 = (c1 >= 0) ? __expf(l1 - mx) : 0.f;
        float a2 = (c2 >= 0) ? __expf(l2 - mx) : 0.f;
        float a3 = (c3 >= 0) ? __expf(l3 - mx) : 0.f;
        float inv = 1.f / (a0 + a1 + a2 + a3);
        a0 *= inv; a1 *= inv; a2 *= inv; a3 *= inv;

        float2 ht;
        ht.x = a0 * ch0.x + a1 * ch1.x + a2 * ch2.x + a3 * ch3.x;
        ht.y = a0 * ch0.y + a1 * ch1.y + a2 * ch2.y + a3 * ch3.y;

        ((float2*)svw)[lane] = ht;
        __syncwarp();

        // z/r GEMVs: two 32-deep accumulator chains
        float2 accz0 = make_float2(0.f, 0.f), accz1 = make_float2(0.f, 0.f);
        float2 accr0 = make_float2(0.f, 0.f), accr1 = make_float2(0.f, 0.f);
#pragma unroll 4
        for (int hp = 0; hp < 32; hp++) {
            float  b0  = svw[hp];
            float  b1  = svw[hp + 32];
            float2 uzA = *(const float2*)(sUz + hp        * UPITCH + 2 * lane);
            float2 uzB = *(const float2*)(sUz + (hp + 32) * UPITCH + 2 * lane);
            float2 urA = *(const float2*)(sUr + hp        * UPITCH + 2 * lane);
            float2 urB = *(const float2*)(sUr + (hp + 32) * UPITCH + 2 * lane);
            accz0.x += b0 * uzA.x; accz0.y += b0 * uzA.y;
            accz1.x += b1 * uzB.x; accz1.y += b1 * uzB.y;
            accr0.x += b0 * urA.x; accr0.y += b0 * urA.y;
            accr1.x += b1 * urB.x; accr1.y += b1 * urB.y;
        }
        float2 z = make_float2(sigm(az.x + accz0.x + accz1.x), sigm(az.y + accz0.y + accz1.y));
        float2 r = make_float2(sigm(ar.x + accr0.x + accr1.x), sigm(ar.y + accr0.y + accr1.y));

        __syncwarp();
        ((float2*)svw)[lane] = make_float2(r.x * ht.x, r.y * ht.y);
        __syncwarp();

        float2 accc0 = make_float2(0.f, 0.f), accc1 = make_float2(0.f, 0.f);
#pragma unroll 4
        for (int hp = 0; hp < 32; hp++) {
            float  b0  = svw[hp];
            float  b1  = svw[hp + 32];
            float2 uhA = *(const float2*)(sUh + hp        * UPITCH + 2 * lane);
            float2 uhB = *(const float2*)(sUh + (hp + 32) * UPITCH + 2 * lane);
            accc0.x += b0 * uhA.x; accc0.y += b0 * uhA.y;
            accc1.x += b1 * uhB.x; accc1.y += b1 * uhB.y;
        }
        float2 cv = make_float2(tanhf(ah.x + accc0.x + accc1.x), tanhf(ah.y + accc0.y + accc1.y));
        float2 hv;
        hv.x = z.x * ht.x + (1.f - z.x) * cv.x;
        hv.y = z.y * ht.y + (1.f - z.y) * cv.y;
        stcg_f2((float2*)(g_h + (size_t)(NL + p) * H) + lane, hv);   // publishes itself
    }
}

// ---------------- kernel 4: per-column max over parents (256 blocks x 32 rows) ----------------
__global__ void k_rmax() {
    __shared__ float sred[4][64];
    int tid = threadIdx.x;               // 256
    int h2 = tid & 63, g = tid >> 6;
    int p0 = blockIdx.x * 32;
    float m = -1e30f;
    for (int r = g; r < 32; r += 4)
        m = fmaxf(m, g_h[(size_t)(NL + p0 + r) * H + h2]);
    sred[g][h2] = m;
    __syncthreads();
    if (tid < 64) {
        float mm = fmaxf(fmaxf(sred[0][tid], sred[1][tid]),
                         fmaxf(sred[2][tid], sred[3][tid]));
        g_partial[blockIdx.x * 64 + tid] = mm;
    }
}

// ---------------- kernel 5: final max + logits + softmax ----------------
__global__ void k_final(const float* __restrict__ Wout, const float* __restrict__ bout,
                        float* __restrict__ out) {
    __shared__ float sred[4][64];
    __shared__ float fm[64];
    __shared__ float lg[4];
    int tid = threadIdx.x;               // 256
    int col = tid & 63, g = tid >> 6;
    float m = -1e30f;
    for (int b = g; b < 256; b += 4)
        m = fmaxf(m, g_partial[b * 64 + col]);
    sred[g][col] = m;
    __syncthreads();
    if (tid < 64)
        fm[tid] = fmaxf(fmaxf(sred[0][tid], sred[1][tid]),
                        fmaxf(sred[2][tid], sred[3][tid]));
    __syncthreads();
    if (tid < NCLASS) {
        float s = bout[tid];
        for (int h = 0; h < 64; h++) s += Wout[tid * 64 + h] * fm[h];
        lg[tid] = s;
    }
    __syncthreads();
    if (tid == 0) {
        float mx = fmaxf(fmaxf(lg[0], lg[1]), fmaxf(lg[2], lg[3]));
        float e0 = __expf(lg[0] - mx), e1 = __expf(lg[1] - mx);
        float e2 = __expf(lg[2] - mx), e3 = __expf(lg[3] - mx);
        float s = e0 + e1 + e2 + e3;
        out[0] = e0 / s; out[1] = e1 / s; out[2] = e2 / s; out[3] = e3 / s;
    }
}

// ---------------- launch ----------------
extern "C" void kernel_launch(void* const* d_in, const int* in_sizes, int n_in,
                              void* d_out, int out_size) {
    const float* x_word  = (const float*)d_in[0];
    const int*   x_index = (const int*)  d_in[1];
    const int*   tree    = (const int*)  d_in[2];
    const float* E       = (const float*)d_in[3];
    const float* Wz      = (const float*)d_in[4];
    const float* Uz      = (const float*)d_in[5];
    const float* bz      = (const float*)d_in[6];
    const float* Wr      = (const float*)d_in[7];
    const float* Ur      = (const float*)d_in[8];
    const float* br      = (const float*)d_in[9];
    const float* Wh      = (const float*)d_in[10];
    const float* Uh      = (const float*)d_in[11];
    const float* bh      = (const float*)d_in[12];
    const float* Wa      = (const float*)d_in[13];
    const float* Wout    = (const float*)d_in[14];
    const float* bout    = (const float*)d_in[15];
    float* out = (float*)d_out;

    const int smemMain = (3 * 64 * UPITCH + 8 * 64) * 4;            // 52736 B
    cudaFuncSetAttribute(k_main, cudaFuncAttributeMaxDynamicSharedMemorySize, smemMain);

    int dev = 0;
    cudaGetDevice(&dev);
    int sms = 0;
    if (cudaDeviceGetAttribute(&sms, cudaDevAttrMultiProcessorCount, dev) != cudaSuccess || sms <= 0)
        sms = 148;
    int nb = 0;
    if (cudaOccupancyMaxActiveBlocksPerMultiprocessor(&nb, k_main, 256, smemMain) != cudaSuccess || nb < 1)
        nb = 1;
    int pgrid = sms * nb;                  // guaranteed co-resident
    if (pgrid > NP / 8) pgrid = NP / 8;
    if (pgrid < 1) pgrid = 1;

    k_prep<<<4 + (NN * H / 4 + 255) / 256, 256>>>(Wz, Wr, Wh, Wa);
    k_transpose<<<3125, 256>>>(E);
    k_embed<<<2048, 256>>>(x_word, x_index);
    k_main<<<pgrid, 256, smemMain>>>(Uz, Ur, Uh, tree, bz, br, bh);
    k_rmax<<<256, 256>>>();
    k_final<<<1, 256>>>(Wout, bout, out);
}

// round 14
// speedup vs baseline: 1.7447x; 1.0461x over previous
#include <cuda_runtime.h>
#include <cstdint>

#define NN      16384      // N_NODES
#define NP      8192       // N_PARENTS
#define NL      8192       // leaves
#define KW      32
#define H       64
#define VOCAB   100000
#define NCLASS  4

#define WPITCH  65         // smem pitch for scalar-read weight tiles (conflict-free)
#define UPITCH  66         // smem pitch for float2-read U tiles (even, conflict-free)
#define LEAFB   256        // leaf-phase blocks (32 leaves each)
#define FULLM   0xffffffffu
#define MAGIC   0x7f800001u   // sNaN bit pattern: impossible as a finite GRU output

// ---------------- device scratch (no allocations allowed) ----------------
__device__ __align__(16) float g_ET[(size_t)VOCAB * H];   // 25.6 MB  E transposed
__device__ __align__(16) float g_xe[(size_t)NN * H];      // 4 MB     xe
__device__ __align__(16) float g_h [(size_t)NN * H];      // 4 MB     node_h (sentinel-init)
__device__ __align__(16) float g_WT[4 * H * H];           // 64 KB    Wz^T,Wr^T,Wh^T,Wa (in,out)
__device__ float g_partial[256 * H];                      // rmax partials

__device__ __forceinline__ float sigm(float x) { return 1.f / (1.f + __expf(-x)); }

// poll load: L2-coherent, never hoisted
__device__ __forceinline__ uint2 ldcg_u2(const void* p) {
    uint2 v;
    asm volatile("ld.global.cg.v2.u32 {%0,%1}, [%2];"
                 : "=r"(v.x), "=r"(v.y) : "l"(p) : "memory");
    return v;
}
__device__ __forceinline__ void stcg_f2(void* p, float2 v) {
    asm volatile("st.global.cg.v2.f32 [%0], {%1,%2};"
                 :: "l"(p), "f"(v.x), "f"(v.y) : "memory");
}
__device__ __forceinline__ void stcg_f1(void* p, float v) {
    asm volatile("st.global.cg.f32 [%0], %1;" :: "l"(p), "f"(v) : "memory");
}

// ---------------- kernel 0: build WT + sentinel-init g_h ----------------
// Wz/Wr/Wh stored transposed WT[h][h2]=W[h2][h] (xe @ W^T); Wa stored DIRECT (xe @ Wa).
__global__ void k_prep(const float* __restrict__ Wz, const float* __restrict__ Wr,
                       const float* __restrict__ Wh, const float* __restrict__ Wa) {
    if (blockIdx.x < 3) {
        __shared__ float t[64][65];
        const float* W = (blockIdx.x == 0) ? Wz : (blockIdx.x == 1) ? Wr : Wh;
        int tid = threadIdx.x;
        for (int i = tid; i < 4096; i += 256) {
            int r = i >> 6, c = i & 63;
            t[r][c] = W[i];
        }
        __syncthreads();
        float* WT = g_WT + blockIdx.x * 4096;
        for (int i = tid; i < 4096; i += 256) {
            int h = i >> 6, h2 = i & 63;
            WT[i] = t[h2][h];
        }
    } else if (blockIdx.x == 3) {
        int tid = threadIdx.x;
        float* WT = g_WT + 3 * 4096;
        for (int i = tid; i < 4096; i += 256)
            WT[i] = Wa[i];
    } else {
        // sentinel-init g_h: 16384*64 floats = 262144 uint4
        int i = (blockIdx.x - 4) * 256 + threadIdx.x;
        if (i < (NN * H / 4))
            ((uint4*)g_h)[i] = make_uint4(MAGIC, MAGIC, MAGIC, MAGIC);
    }
}

// ---------------- kernel 1: transpose E (H, VOCAB) -> (VOCAB, H) ----------------
__global__ void k_transpose(const float* __restrict__ E) {
    __shared__ float sm[64][33];
    int v0 = blockIdx.x * 32;
    int tid = threadIdx.x;
    int vv = tid & 31, hh = tid >> 5;
#pragma unroll
    for (int h0 = 0; h0 < 64; h0 += 8)
        sm[h0 + hh][vv] = E[(size_t)(h0 + hh) * VOCAB + v0 + vv];
    __syncthreads();
#pragma unroll
    for (int i = tid; i < 2048; i += 256) {
        int v = i >> 6, h = i & 63;
        g_ET[(size_t)(v0 + v) * H + h] = sm[h][v];
    }
}

// ---------------- kernel 2: xe[n,h] = sum_k x_word[n,k] * E_T[idx[n,k], h] ----------------
__global__ void __launch_bounds__(256) k_embed(const float* __restrict__ xw,
                                               const int* __restrict__ xi) {
    int warp = (blockIdx.x * blockDim.x + threadIdx.x) >> 5;
    int lane = threadIdx.x & 31;
    if (warp >= NN) return;
    float w  = xw[warp * KW + lane];
    int   ix = xi[warp * KW + lane];
    float2 acc = make_float2(0.f, 0.f);
#pragma unroll 4
    for (int j = 0; j < 32; j++) {
        int   idx = __shfl_sync(FULLM, ix, j);
        float wj  = __shfl_sync(FULLM, w,  j);
        float2 e = *(const float2*)(&g_ET[(size_t)idx * H + 2 * lane]);
        acc.x += wj * e.x;
        acc.y += wj * e.y;
    }
    *(float2*)(&g_xe[(size_t)warp * H + 2 * lane]) = acc;
}

// ---------------- kernel 3: persistent main — BYTE-EXACT R9 (74.7us measured) ----------------
__global__ void __launch_bounds__(256, 4) k_main(const float* __restrict__ Uz,
                                                 const float* __restrict__ Ur,
                                                 const float* __restrict__ Uh,
                                                 const int*   __restrict__ tree,
                                                 const float* __restrict__ Wz,
                                                 const float* __restrict__ Wh,
                                                 const float* __restrict__ bz,
                                                 const float* __restrict__ br,
                                                 const float* __restrict__ bh) {
    extern __shared__ float sm[];
    int tid = threadIdx.x;
    int wid = tid >> 5, lane = tid & 31;

    // ================= leaf phase (blocks 0..LEAFB-1) =================
    if (blockIdx.x < LEAFB) {
        float* sW = sm;                         // 2 * 64 * WPITCH
        float* sb = sW + 2 * 64 * WPITCH;       // 2 * 64
        float* sx = sb + 2 * 64;                // 32 * 64

        for (int m = 0; m < 2; m++) {
            const float* W = m ? Wh : Wz;
            for (int i = tid; i < 4096; i += 256) {
                int h2 = i >> 6, h = i & 63;
                sW[m * 64 * WPITCH + h * WPITCH + h2] = W[i];
            }
        }
        if (tid < 64) { sb[tid] = bz[tid]; sb[64 + tid] = bh[tid]; }

        int base = blockIdx.x * 32;
        for (int i = tid; i < 32 * 64; i += 256)
            sx[i] = g_xe[(size_t)base * H + i];
        __syncthreads();

        int h2 = tid & 63, grp = tid >> 6;
        const float* x0 = sx + grp * 8 * 64;
        float az[8] = {0,0,0,0,0,0,0,0}, ah[8] = {0,0,0,0,0,0,0,0};
#pragma unroll 4
        for (int h = 0; h < 64; h++) {
            float wz = sW[h * WPITCH + h2];
            float wh = sW[64 * WPITCH + h * WPITCH + h2];
#pragma unroll
            for (int nb = 0; nb < 8; nb++) {
                float x = x0[nb * 64 + h];
                az[nb] += x * wz; ah[nb] += x * wh;
            }
        }
#pragma unroll
        for (int nb = 0; nb < 8; nb++) {
            int gn = base + grp * 8 + nb;
            float z = sigm(az[nb] + sb[h2]);
            float c = tanhf(ah[nb] + sb[64 + h2]);
            stcg_f1(&g_h[(size_t)gn * H + h2], (1.f - z) * c);   // publishes itself
        }
        __syncthreads();                        // before smem reuse below
    }

    // ================= parent phase (all blocks) =================
    float* sU = sm;                          // 3 * 64 * UPITCH, input-major (U^T)
    float* sv = sU + 3 * 64 * UPITCH;        // 8 warps * 64

    const float* Us[3] = {Uz, Ur, Uh};
    for (int m = 0; m < 3; m++) {
        const float* U = Us[m];
        for (int i = tid; i < 4096; i += 256) {
            int h2 = i >> 6, h = i & 63;
            sU[m * 64 * UPITCH + h * UPITCH + h2] = U[i];
        }
    }
    __syncthreads();

    int gwarp = blockIdx.x * 8 + wid;
    int nwarp = gridDim.x * 8;
    float* svw = sv + wid * 64;
    const float* sUz = sU;
    const float* sUr = sU + 64 * UPITCH;
    const float* sUh = sU + 2 * 64 * UPITCH;

    float2 bz2 = __ldg((const float2*)bz + lane);
    float2 br2 = __ldg((const float2*)br + lane);
    float2 bh2 = __ldg((const float2*)bh + lane);

    for (int p = gwarp; p < NP; p += nwarp) {
        const int* tr = tree + (size_t)p * 5;
        int c0 = __ldg(tr + 0), c1 = __ldg(tr + 1), c2 = __ldg(tr + 2), c3 = __ldg(tr + 3);

        // ---- fused A precompute: az/ar/ah = xe@W^T + b ; aq = xe@Wa ----
        float2 xe2 = __ldcg((const float2*)(g_xe + (size_t)(NL + p) * H) + lane);
        float2 az = bz2, ar = br2, ah = bh2, aq = make_float2(0.f, 0.f);
#pragma unroll 8
        for (int h = 0; h < 64; h++) {
            float b = __shfl_sync(FULLM, (h & 1) ? xe2.y : xe2.x, h >> 1);
            float2 wz = __ldg((const float2*)(g_WT            + h * 64) + lane);
            float2 wr = __ldg((const float2*)(g_WT + 1 * 4096 + h * 64) + lane);
            float2 wh = __ldg((const float2*)(g_WT + 2 * 4096 + h * 64) + lane);
            float2 wa = __ldg((const float2*)(g_WT + 3 * 4096 + h * 64) + lane);
            az.x += b * wz.x; az.y += b * wz.y;
            ar.x += b * wr.x; ar.y += b * wr.y;
            ah.x += b * wh.x; ah.y += b * wh.y;
            aq.x += b * wa.x; aq.y += b * wa.y;
        }

        // ---- data-as-flag poll: each lane waits on its own 8B of each child ----
        const void* p0 = (const uint2*)(g_h + (size_t)(c0 < 0 ? 0 : c0) * H) + lane;
        const void* p1 = (const uint2*)(g_h + (size_t)(c1 < 0 ? 0 : c1) * H) + lane;
        const void* p2 = (const uint2*)(g_h + (size_t)(c2 < 0 ? 0 : c2) * H) + lane;
        const void* p3 = (const uint2*)(g_h + (size_t)(c3 < 0 ? 0 : c3) * H) + lane;
        uint2 v0, v1, v2, v3;
        bool r0 = (c0 < 0), r1 = (c1 < 0), r2 = (c2 < 0), r3 = (c3 < 0);
        for (;;) {
            if (!r0) { v0 = ldcg_u2(p0); r0 = (v0.x != MAGIC) && (v0.y != MAGIC); }
            if (!r1) { v1 = ldcg_u2(p1); r1 = (v1.x != MAGIC) && (v1.y != MAGIC); }
            if (!r2) { v2 = ldcg_u2(p2); r2 = (v2.x != MAGIC) && (v2.y != MAGIC); }
            if (!r3) { v3 = ldcg_u2(p3); r3 = (v3.x != MAGIC) && (v3.y != MAGIC); }
            if (r0 && r1 && r2 && r3) break;
            __nanosleep(20);
        }
        float2 ch0 = (c0 >= 0) ? make_float2(__uint_as_float(v0.x), __uint_as_float(v0.y)) : make_float2(0.f, 0.f);
        float2 ch1 = (c1 >= 0) ? make_float2(__uint_as_float(v1.x), __uint_as_float(v1.y)) : make_float2(0.f, 0.f);
        float2 ch2 = (c2 >= 0) ? make_float2(__uint_as_float(v2.x), __uint_as_float(v2.y)) : make_float2(0.f, 0.f);
        float2 ch3 = (c3 >= 0) ? make_float2(__uint_as_float(v3.x), __uint_as_float(v3.y)) : make_float2(0.f, 0.f);

        // attention logits l_j = sigmoid(q . child_j)
        float q0 = aq.x * ch0.x + aq.y * ch0.y;
        float q1 = aq.x * ch1.x + aq.y * ch1.y;
        float q2 = aq.x * ch2.x + aq.y * ch2.y;
        float q3 = aq.x * ch3.x + aq.y * ch3.y;
#pragma unroll
        for (int o = 16; o > 0; o >>= 1) {
            q0 += __shfl_xor_sync(FULLM, q0, o);
            q1 += __shfl_xor_sync(FULLM, q1, o);
            q2 += __shfl_xor_sync(FULLM, q2, o);
            q3 += __shfl_xor_sync(FULLM, q3, o);
        }
        float l0 = (c0 >= 0) ? sigm(q0) : -1e30f;
        float l1 = (c1 >= 0) ? sigm(q1) : -1e30f;
        float l2 = (c2 >= 0) ? sigm(q2) : -1e30f;
        float l3 = (c3 >= 0) ? sigm(q3) : -1e30f;
        float mx = fmaxf(fmaxf(l0, l1), fmaxf(l2, l3));
        float a0 = (c0 >= 0) ? __expf(l0 - mx) : 0.f;
        float a1 = (c1 >= 0) ? __expf(l1 - mx) : 0.f;
        float a2 = (c2 >= 0) ? __expf(l2 - mx) : 0.f;
        float a3 = (c3 >= 0) ? __expf(l3 - mx) : 0.f;
        float inv = 1.f / (a0 + a1 + a2 + a3);
        a0 *= inv; a1 *= inv; a2 *= inv; a3 *= inv;

        float2 ht;
        ht.x = a0 * ch0.x + a1 * ch1.x + a2 * ch2.x + a3 * ch3.x;
        ht.y = a0 * ch0.y + a1 * ch1.y + a2 * ch2.y + a3 * ch3.y;

        ((float2*)svw)[lane] = ht;
        __syncwarp();

        // z/r GEMVs: two 32-deep accumulator chains
        float2 accz0 = make_float2(0.f, 0.f), accz1 = make_float2(0.f, 0.f);
        float2 accr0 = make_float2(0.f, 0.f), accr1 = make_float2(0.f, 0.f);
#pragma unroll 4
        for (int hp = 0; hp < 32; hp++) {
            float  b0  = svw[hp];
            float  b1  = svw[hp + 32];
            float2 uzA = *(const float2*)(sUz + hp        * UPITCH + 2 * lane);
            float2 uzB = *(const float2*)(sUz + (hp + 32) * UPITCH + 2 * lane);
            float2 urA = *(const float2*)(sUr + hp        * UPITCH + 2 * lane);
            float2 urB = *(const float2*)(sUr + (hp + 32) * UPITCH + 2 * lane);
            accz0.x += b0 * uzA.x; accz0.y += b0 * uzA.y;
            accz1.x += b1 * uzB.x; accz1.y += b1 * uzB.y;
            accr0.x += b0 * urA.x; accr0.y += b0 * urA.y;
            accr1.x += b1 * urB.x; accr1.y += b1 * urB.y;
        }
        float2 z = make_float2(sigm(az.x + accz0.x + accz1.x), sigm(az.y + accz0.y + accz1.y));
        float2 r = make_float2(sigm(ar.x + accr0.x + accr1.x), sigm(ar.y + accr0.y + accr1.y));

        __syncwarp();
        ((float2*)svw)[lane] = make_float2(r.x * ht.x, r.y * ht.y);
        __syncwarp();

        float2 accc0 = make_float2(0.f, 0.f), accc1 = make_float2(0.f, 0.f);
#pragma unroll 4
        for (int hp = 0; hp < 32; hp++) {
            float  b0  = svw[hp];
            float  b1  = svw[hp + 32];
            float2 uhA = *(const float2*)(sUh + hp        * UPITCH + 2 * lane);
            float2 uhB = *(const float2*)(sUh + (hp + 32) * UPITCH + 2 * lane);
            accc0.x += b0 * uhA.x; accc0.y += b0 * uhA.y;
            accc1.x += b1 * uhB.x; accc1.y += b1 * uhB.y;
        }
        float2 cv = make_float2(tanhf(ah.x + accc0.x + accc1.x), tanhf(ah.y + accc0.y + accc1.y));
        float2 hv;
        hv.x = z.x * ht.x + (1.f - z.x) * cv.x;
        hv.y = z.y * ht.y + (1.f - z.y) * cv.y;
        stcg_f2((float2*)(g_h + (size_t)(NL + p) * H) + lane, hv);   // publishes itself
    }
}

// ---------------- kernel 4: per-column max over parents (256 blocks x 32 rows) ----------------
__global__ void k_rmax() {
    __shared__ float sred[4][64];
    int tid = threadIdx.x;               // 256
    int h2 = tid & 63, g = tid >> 6;
    int p0 = blockIdx.x * 32;
    float m = -1e30f;
    for (int r = g; r < 32; r += 4)
        m = fmaxf(m, g_h[(size_t)(NL + p0 + r) * H + h2]);
    sred[g][h2] = m;
    __syncthreads();
    if (tid < 64) {
        float mm = fmaxf(fmaxf(sred[0][tid], sred[1][tid]),
                         fmaxf(sred[2][tid], sred[3][tid]));
        g_partial[blockIdx.x * 64 + tid] = mm;
    }
}

// ---------------- kernel 5: final max + logits + softmax ----------------
__global__ void k_final(const float* __restrict__ Wout, const float* __restrict__ bout,
                        float* __restrict__ out) {
    __shared__ float sred[4][64];
    __shared__ float fm[64];
    __shared__ float lg[4];
    int tid = threadIdx.x;               // 256
    int col = tid & 63, g = tid >> 6;
    float m = -1e30f;
    for (int b = g; b < 256; b += 4)
        m = fmaxf(m, g_partial[b * 64 + col]);
    sred[g][col] = m;
    __syncthreads();
    if (tid < 64)
        fm[tid] = fmaxf(fmaxf(sred[0][tid], sred[1][tid]),
                        fmaxf(sred[2][tid], sred[3][tid]));
    __syncthreads();
    if (tid < NCLASS) {
        float s = bout[tid];
        for (int h = 0; h < 64; h++) s += Wout[tid * 64 + h] * fm[h];
        lg[tid] = s;
    }
    __syncthreads();
    if (tid == 0) {
        float mx = fmaxf(fmaxf(lg[0], lg[1]), fmaxf(lg[2], lg[3]));
        float e0 = __expf(lg[0] - mx), e1 = __expf(lg[1] - mx);
        float e2 = __expf(lg[2] - mx), e3 = __expf(lg[3] - mx);
        float s = e0 + e1 + e2 + e3;
        out[0] = e0 / s; out[1] = e1 / s; out[2] = e2 / s; out[3] = e3 / s;
    }
}

// ---------------- launch ----------------
extern "C" void kernel_launch(void* const* d_in, const int* in_sizes, int n_in,
                              void* d_out, int out_size) {
    const float* x_word  = (const float*)d_in[0];
    const int*   x_index = (const int*)  d_in[1];
    const int*   tree    = (const int*)  d_in[2];
    const float* E       = (const float*)d_in[3];
    const float* Wz      = (const float*)d_in[4];
    const float* Uz      = (const float*)d_in[5];
    const float* bz      = (const float*)d_in[6];
    const float* Wr      = (const float*)d_in[7];
    const float* Ur      = (const float*)d_in[8];
    const float* br      = (const float*)d_in[9];
    const float* Wh      = (const float*)d_in[10];
    const float* Uh      = (const float*)d_in[11];
    const float* bh      = (const float*)d_in[12];
    const float* Wa      = (const float*)d_in[13];
    const float* Wout    = (const float*)d_in[14];
    const float* bout    = (const float*)d_in[15];
    float* out = (float*)d_out;

    const int smemMain = (3 * 64 * UPITCH + 8 * 64) * 4;            // 52736 B
    cudaFuncSetAttribute(k_main, cudaFuncAttributeMaxDynamicSharedMemorySize, smemMain);

    int dev = 0;
    cudaGetDevice(&dev);
    int sms = 0;
    if (cudaDeviceGetAttribute(&sms, cudaDevAttrMultiProcessorCount, dev) != cudaSuccess || sms <= 0)
        sms = 148;
    int nb = 0;
    if (cudaOccupancyMaxActiveBlocksPerMultiprocessor(&nb, k_main, 256, smemMain) != cudaSuccess || nb < 1)
        nb = 1;
    int pgrid = sms * nb;                  // guaranteed co-resident
    if (pgrid > NP / 8) pgrid = NP / 8;
    if (pgrid < LEAFB) pgrid = LEAFB;      // all leaf tiles must be covered
    if (pgrid < 1) pgrid = 1;

    k_prep<<<4 + (NN * H / 4 + 255) / 256, 256>>>(Wz, Wr, Wh, Wa);
    k_transpose<<<3125, 256>>>(E);
    k_embed<<<2048, 256>>>(x_word, x_index);
    k_main<<<pgrid, 256, smemMain>>>(Uz, Ur, Uh, tree, Wz, Wh, bz, br, bh);
    k_rmax<<<256, 256>>>();
    k_final<<<1, 256>>>(Wout, bout, out);
}

// round 15
// speedup vs baseline: 1.7465x; 1.0010x over previous
#include <cuda_runtime.h>
#include <cstdint>

#define NN      16384      // N_NODES
#define NP      8192       // N_PARENTS
#define NL      8192       // leaves
#define KW      32
#define H       64
#define VOCAB   100000
#define NCLASS  4

#define WPITCH  65         // smem pitch for scalar-read weight tiles (conflict-free)
#define UPITCH  66         // smem pitch for float2-read U tiles (even, conflict-free)
#define LEAFB   256        // leaf-phase blocks (32 leaves each)
#define FULLM   0xffffffffu
#define MAGIC   0x7f800001u   // sNaN bit pattern: impossible as a finite GRU output

typedef unsigned long long ull;

// ---------------- device scratch (no allocations allowed) ----------------
__device__ __align__(16) float g_ET[(size_t)VOCAB * H];   // 25.6 MB  E transposed
__device__ __align__(16) float g_xe[(size_t)NN * H];      // 4 MB     xe
__device__ __align__(16) float g_h [(size_t)NN * H];      // 4 MB     node_h (sentinel-init)
__device__ __align__(16) float g_WT[4 * H * H];           // 64 KB    Wz^T,Wr^T,Wh^T,Wa (in,out)
__device__ float g_partial[256 * H];                      // rmax partials

__device__ __forceinline__ float sigm(float x) { return 1.f / (1.f + __expf(-x)); }

// ---- packed f32x2 helpers (Blackwell FFMA2; bit-identical to two rn FMAs) ----
__device__ __forceinline__ ull pack2(float x, float y) {
    ull r; asm("mov.b64 %0, {%1,%2};" : "=l"(r) : "f"(x), "f"(y)); return r;
}
__device__ __forceinline__ ull dup2(float x) {
    ull r; asm("mov.b64 %0, {%1,%1};" : "=l"(r) : "f"(x)); return r;
}
__device__ __forceinline__ void unpack2(ull v, float& x, float& y) {
    asm("mov.b64 {%0,%1}, %2;" : "=f"(x), "=f"(y) : "l"(v));
}
__device__ __forceinline__ ull fma2(ull a, ull b, ull c) {
    ull d; asm("fma.rn.f32x2 %0, %1, %2, %3;" : "=l"(d) : "l"(a), "l"(b), "l"(c)); return d;
}

// poll load: L2-coherent, never hoisted
__device__ __forceinline__ uint2 ldcg_u2(const void* p) {
    uint2 v;
    asm volatile("ld.global.cg.v2.u32 {%0,%1}, [%2];"
                 : "=r"(v.x), "=r"(v.y) : "l"(p) : "memory");
    return v;
}
__device__ __forceinline__ void stcg_f2(void* p, float2 v) {
    asm volatile("st.global.cg.v2.f32 [%0], {%1,%2};"
                 :: "l"(p), "f"(v.x), "f"(v.y) : "memory");
}
__device__ __forceinline__ void stcg_f1(void* p, float v) {
    asm volatile("st.global.cg.f32 [%0], %1;" :: "l"(p), "f"(v) : "memory");
}

// ---------------- kernel 0: build WT + sentinel-init g_h ----------------
// Wz/Wr/Wh stored transposed WT[h][h2]=W[h2][h] (xe @ W^T); Wa stored DIRECT (xe @ Wa).
__global__ void k_prep(const float* __restrict__ Wz, const float* __restrict__ Wr,
                       const float* __restrict__ Wh, const float* __restrict__ Wa) {
    if (blockIdx.x < 3) {
        __shared__ float t[64][65];
        const float* W = (blockIdx.x == 0) ? Wz : (blockIdx.x == 1) ? Wr : Wh;
        int tid = threadIdx.x;
        for (int i = tid; i < 4096; i += 256) {
            int r = i >> 6, c = i & 63;
            t[r][c] = W[i];
        }
        __syncthreads();
        float* WT = g_WT + blockIdx.x * 4096;
        for (int i = tid; i < 4096; i += 256) {
            int h = i >> 6, h2 = i & 63;
            WT[i] = t[h2][h];
        }
    } else if (blockIdx.x == 3) {
        int tid = threadIdx.x;
        float* WT = g_WT + 3 * 4096;
        for (int i = tid; i < 4096; i += 256)
            WT[i] = Wa[i];
    } else {
        // sentinel-init g_h: 16384*64 floats = 262144 uint4
        int i = (blockIdx.x - 4) * 256 + threadIdx.x;
        if (i < (NN * H / 4))
            ((uint4*)g_h)[i] = make_uint4(MAGIC, MAGIC, MAGIC, MAGIC);
    }
}

// ---------------- kernel 1: transpose E (H, VOCAB) -> (VOCAB, H) ----------------
__global__ void k_transpose(const float* __restrict__ E) {
    __shared__ float sm[64][33];
    int v0 = blockIdx.x * 32;
    int tid = threadIdx.x;
    int vv = tid & 31, hh = tid >> 5;
#pragma unroll
    for (int h0 = 0; h0 < 64; h0 += 8)
        sm[h0 + hh][vv] = E[(size_t)(h0 + hh) * VOCAB + v0 + vv];
    __syncthreads();
#pragma unroll
    for (int i = tid; i < 2048; i += 256) {
        int v = i >> 6, h = i & 63;
        g_ET[(size_t)(v0 + v) * H + h] = sm[h][v];
    }
}

// ---------------- kernel 2: xe[n,h] = sum_k x_word[n,k] * E_T[idx[n,k], h] ----------------
__global__ void __launch_bounds__(256) k_embed(const float* __restrict__ xw,
                                               const int* __restrict__ xi) {
    int warp = (blockIdx.x * blockDim.x + threadIdx.x) >> 5;
    int lane = threadIdx.x & 31;
    if (warp >= NN) return;
    float w  = xw[warp * KW + lane];
    int   ix = xi[warp * KW + lane];
    float2 acc = make_float2(0.f, 0.f);
#pragma unroll 4
    for (int j = 0; j < 32; j++) {
        int   idx = __shfl_sync(FULLM, ix, j);
        float wj  = __shfl_sync(FULLM, w,  j);
        float2 e = *(const float2*)(&g_ET[(size_t)idx * H + 2 * lane]);
        acc.x += wj * e.x;
        acc.y += wj * e.y;
    }
    *(float2*)(&g_xe[(size_t)warp * H + 2 * lane]) = acc;
}

// ---------------- kernel 3: persistent main (R9 structure; hot loops FFMA2-packed) ----------------
__global__ void __launch_bounds__(256, 4) k_main(const float* __restrict__ Uz,
                                                 const float* __restrict__ Ur,
                                                 const float* __restrict__ Uh,
                                                 const int*   __restrict__ tree,
                                                 const float* __restrict__ Wz,
                                                 const float* __restrict__ Wh,
                                                 const float* __restrict__ bz,
                                                 const float* __restrict__ br,
                                                 const float* __restrict__ bh) {
    extern __shared__ float sm[];
    int tid = threadIdx.x;
    int wid = tid >> 5, lane = tid & 31;

    // ================= leaf phase (blocks 0..LEAFB-1) — byte-identical to R9 =================
    if (blockIdx.x < LEAFB) {
        float* sW = sm;                         // 2 * 64 * WPITCH
        float* sb = sW + 2 * 64 * WPITCH;       // 2 * 64
        float* sx = sb + 2 * 64;                // 32 * 64

        for (int m = 0; m < 2; m++) {
            const float* W = m ? Wh : Wz;
            for (int i = tid; i < 4096; i += 256) {
                int h2 = i >> 6, h = i & 63;
                sW[m * 64 * WPITCH + h * WPITCH + h2] = W[i];
            }
        }
        if (tid < 64) { sb[tid] = bz[tid]; sb[64 + tid] = bh[tid]; }

        int base = blockIdx.x * 32;
        for (int i = tid; i < 32 * 64; i += 256)
            sx[i] = g_xe[(size_t)base * H + i];
        __syncthreads();

        int h2 = tid & 63, grp = tid >> 6;
        const float* x0 = sx + grp * 8 * 64;
        float az[8] = {0,0,0,0,0,0,0,0}, ah[8] = {0,0,0,0,0,0,0,0};
#pragma unroll 4
        for (int h = 0; h < 64; h++) {
            float wz = sW[h * WPITCH + h2];
            float wh = sW[64 * WPITCH + h * WPITCH + h2];
#pragma unroll
            for (int nb = 0; nb < 8; nb++) {
                float x = x0[nb * 64 + h];
                az[nb] += x * wz; ah[nb] += x * wh;
            }
        }
#pragma unroll
        for (int nb = 0; nb < 8; nb++) {
            int gn = base + grp * 8 + nb;
            float z = sigm(az[nb] + sb[h2]);
            float c = tanhf(ah[nb] + sb[64 + h2]);
            stcg_f1(&g_h[(size_t)gn * H + h2], (1.f - z) * c);   // publishes itself
        }
        __syncthreads();                        // before smem reuse below
    }

    // ================= parent phase (all blocks) =================
    float* sU = sm;                          // 3 * 64 * UPITCH, input-major (U^T)
    float* sv = sU + 3 * 64 * UPITCH;        // 8 warps * 64

    const float* Us[3] = {Uz, Ur, Uh};
    for (int m = 0; m < 3; m++) {
        const float* U = Us[m];
        for (int i = tid; i < 4096; i += 256) {
            int h2 = i >> 6, h = i & 63;
            sU[m * 64 * UPITCH + h * UPITCH + h2] = U[i];
        }
    }
    __syncthreads();

    int gwarp = blockIdx.x * 8 + wid;
    int nwarp = gridDim.x * 8;
    float* svw = sv + wid * 64;
    const float* sUz = sU;
    const float* sUr = sU + 64 * UPITCH;
    const float* sUh = sU + 2 * 64 * UPITCH;

    float2 bz2 = __ldg((const float2*)bz + lane);
    float2 br2 = __ldg((const float2*)br + lane);
    float2 bh2 = __ldg((const float2*)bh + lane);

    for (int p = gwarp; p < NP; p += nwarp) {
        const int* tr = tree + (size_t)p * 5;
        int c0 = __ldg(tr + 0), c1 = __ldg(tr + 1), c2 = __ldg(tr + 2), c3 = __ldg(tr + 3);

        // ---- fused A precompute (FFMA2-packed): az/ar/ah = xe@W^T + b ; aq = xe@Wa ----
        float2 xe2 = __ldcg((const float2*)(g_xe + (size_t)(NL + p) * H) + lane);
        ull az = pack2(bz2.x, bz2.y);
        ull ar = pack2(br2.x, br2.y);
        ull ah = pack2(bh2.x, bh2.y);
        ull aq = 0ull;
#pragma unroll 8
        for (int h = 0; h < 64; h++) {
            float b = __shfl_sync(FULLM, (h & 1) ? xe2.y : xe2.x, h >> 1);
            ull bb = dup2(b);
            ull wz = __ldg((const ull*)(g_WT            + h * 64) + lane);
            ull wr = __ldg((const ull*)(g_WT + 1 * 4096 + h * 64) + lane);
            ull wh = __ldg((const ull*)(g_WT + 2 * 4096 + h * 64) + lane);
            ull wa = __ldg((const ull*)(g_WT + 3 * 4096 + h * 64) + lane);
            az = fma2(bb, wz, az);
            ar = fma2(bb, wr, ar);
            ah = fma2(bb, wh, ah);
            aq = fma2(bb, wa, aq);
        }
        float azx, azy, arx, ary, ahx, ahy, aqx, aqy;
        unpack2(az, azx, azy);
        unpack2(ar, arx, ary);
        unpack2(ah, ahx, ahy);
        unpack2(aq, aqx, aqy);

        // ---- data-as-flag poll: each lane waits on its own 8B of each child ----
        const void* p0 = (const uint2*)(g_h + (size_t)(c0 < 0 ? 0 : c0) * H) + lane;
        const void* p1 = (const uint2*)(g_h + (size_t)(c1 < 0 ? 0 : c1) * H) + lane;
        const void* p2 = (const uint2*)(g_h + (size_t)(c2 < 0 ? 0 : c2) * H) + lane;
        const void* p3 = (const uint2*)(g_h + (size_t)(c3 < 0 ? 0 : c3) * H) + lane;
        uint2 v0, v1, v2, v3;
        bool r0 = (c0 < 0), r1 = (c1 < 0), r2 = (c2 < 0), r3 = (c3 < 0);
        for (;;) {
            if (!r0) { v0 = ldcg_u2(p0); r0 = (v0.x != MAGIC) && (v0.y != MAGIC); }
            if (!r1) { v1 = ldcg_u2(p1); r1 = (v1.x != MAGIC) && (v1.y != MAGIC); }
            if (!r2) { v2 = ldcg_u2(p2); r2 = (v2.x != MAGIC) && (v2.y != MAGIC); }
            if (!r3) { v3 = ldcg_u2(p3); r3 = (v3.x != MAGIC) && (v3.y != MAGIC); }
            if (r0 && r1 && r2 && r3) break;
            __nanosleep(20);
        }
        float2 ch0 = (c0 >= 0) ? make_float2(__uint_as_float(v0.x), __uint_as_float(v0.y)) : make_float2(0.f, 0.f);
        float2 ch1 = (c1 >= 0) ? make_float2(__uint_as_float(v1.x), __uint_as_float(v1.y)) : make_float2(0.f, 0.f);
        float2 ch2 = (c2 >= 0) ? make_float2(__uint_as_float(v2.x), __uint_as_float(v2.y)) : make_float2(0.f, 0.f);
        float2 ch3 = (c3 >= 0) ? make_float2(__uint_as_float(v3.x), __uint_as_float(v3.y)) : make_float2(0.f, 0.f);

        // attention logits l_j = sigmoid(q . child_j)
        float q0 = aqx * ch0.x + aqy * ch0.y;
        float q1 = aqx * ch1.x + aqy * ch1.y;
        float q2 = aqx * ch2.x + aqy * ch2.y;
        float q3 = aqx * ch3.x + aqy * ch3.y;
#pragma unroll
        for (int o = 16; o > 0; o >>= 1) {
            q0 += __shfl_xor_sync(FULLM, q0, o);
            q1 += __shfl_xor_sync(FULLM, q1, o);
            q2 += __shfl_xor_sync(FULLM, q2, o);
            q3 += __shfl_xor_sync(FULLM, q3, o);
        }
        float l0 = (c0 >= 0) ? sigm(q0) : -1e30f;
        float l1 = (c1 >= 0) ? sigm(q1) : -1e30f;
        float l2 = (c2 >= 0) ? sigm(q2) : -1e30f;
        float l3 = (c3 >= 0) ? sigm(q3) : -1e30f;
        float mx = fmaxf(fmaxf(l0, l1), fmaxf(l2, l3));
        float a0 = (c0 >= 0) ? __expf(l0 - mx) : 0.f;
        float a1 = (c1 >= 0) ? __expf(l1 - mx) : 0.f;
        float a2 = (c2 >= 0) ? __expf(l2 - mx) : 0.f;
        float a3 = (c3 >= 0) ? __expf(l3 - mx) : 0.f;
        float inv = 1.f / (a0 + a1 + a2 + a3);
        a0 *= inv; a1 *= inv; a2 *= inv; a3 *= inv;

        float2 ht;
        ht.x = a0 * ch0.x + a1 * ch1.x + a2 * ch2.x + a3 * ch3.x;
        ht.y = a0 * ch0.y + a1 * ch1.y + a2 * ch2.y + a3 * ch3.y;

        ((float2*)svw)[lane] = ht;
        __syncwarp();

        // z/r GEMVs (FFMA2-packed): two 32-deep packed accumulator chains
        ull accz0 = 0ull, accz1 = 0ull, accr0 = 0ull, accr1 = 0ull;
#pragma unroll 4
        for (int hp = 0; hp < 32; hp++) {
            float b0 = svw[hp];
            float b1 = svw[hp + 32];
            ull bb0 = dup2(b0);
            ull bb1 = dup2(b1);
            ull uzA = *(const ull*)(sUz + hp        * UPITCH + 2 * lane);
            ull uzB = *(const ull*)(sUz + (hp + 32) * UPITCH + 2 * lane);
            ull urA = *(const ull*)(sUr + hp        * UPITCH + 2 * lane);
            ull urB = *(const ull*)(sUr + (hp + 32) * UPITCH + 2 * lane);
            accz0 = fma2(bb0, uzA, accz0);
            accz1 = fma2(bb1, uzB, accz1);
            accr0 = fma2(bb0, urA, accr0);
            accr1 = fma2(bb1, urB, accr1);
        }
        float az0x, az0y, az1x, az1y, ar0x, ar0y, ar1x, ar1y;
        unpack2(accz0, az0x, az0y); unpack2(accz1, az1x, az1y);
        unpack2(accr0, ar0x, ar0y); unpack2(accr1, ar1x, ar1y);
        float2 z = make_float2(sigm(azx + az0x + az1x), sigm(azy + az0y + az1y));
        float2 r = make_float2(sigm(arx + ar0x + ar1x), sigm(ary + ar0y + ar1y));

        __syncwarp();
        ((float2*)svw)[lane] = make_float2(r.x * ht.x, r.y * ht.y);
        __syncwarp();

        // c GEMV (FFMA2-packed)
        ull accc0 = 0ull, accc1 = 0ull;
#pragma unroll 4
        for (int hp = 0; hp < 32; hp++) {
            float b0 = svw[hp];
            float b1 = svw[hp + 32];
            ull bb0 = dup2(b0);
            ull bb1 = dup2(b1);
            ull uhA = *(const ull*)(sUh + hp        * UPITCH + 2 * lane);
            ull uhB = *(const ull*)(sUh + (hp + 32) * UPITCH + 2 * lane);
            accc0 = fma2(bb0, uhA, accc0);
            accc1 = fma2(bb1, uhB, accc1);
        }
        float ac0x, ac0y, ac1x, ac1y;
        unpack2(accc0, ac0x, ac0y); unpack2(accc1, ac1x, ac1y);
        float2 cv = make_float2(tanhf(ahx + ac0x + ac1x), tanhf(ahy + ac0y + ac1y));
        float2 hv;
        hv.x = z.x * ht.x + (1.f - z.x) * cv.x;
        hv.y = z.y * ht.y + (1.f - z.y) * cv.y;
        stcg_f2((float2*)(g_h + (size_t)(NL + p) * H) + lane, hv);   // publishes itself
    }
}

// ---------------- kernel 4: per-column max over parents (256 blocks x 32 rows) ----------------
__global__ void k_rmax() {
    __shared__ float sred[4][64];
    int tid = threadIdx.x;               // 256
    int h2 = tid & 63, g = tid >> 6;
    int p0 = blockIdx.x * 32;
    float m = -1e30f;
    for (int r = g; r < 32; r += 4)
        m = fmaxf(m, g_h[(size_t)(NL + p0 + r) * H + h2]);
    sred[g][h2] = m;
    __syncthreads();
    if (tid < 64) {
        float mm = fmaxf(fmaxf(sred[0][tid], sred[1][tid]),
                         fmaxf(sred[2][tid], sred[3][tid]));
        g_partial[blockIdx.x * 64 + tid] = mm;
    }
}

// ---------------- kernel 5: final max + logits + softmax ----------------
__global__ void k_final(const float* __restrict__ Wout, const float* __restrict__ bout,
                        float* __restrict__ out) {
    __shared__ float sred[4][64];
    __shared__ float fm[64];
    __shared__ float lg[4];
    int tid = threadIdx.x;               // 256
    int col = tid & 63, g = tid >> 6;
    float m = -1e30f;
    for (int b = g; b < 256; b += 4)
        m = fmaxf(m, g_partial[b * 64 + col]);
    sred[g][col] = m;
    __syncthreads();
    if (tid < 64)
        fm[tid] = fmaxf(fmaxf(sred[0][tid], sred[1][tid]),
                        fmaxf(sred[2][tid], sred[3][tid]));
    __syncthreads();
    if (tid < NCLASS) {
        float s = bout[tid];
        for (int h = 0; h < 64; h++) s += Wout[tid * 64 + h] * fm[h];
        lg[tid] = s;
    }
    __syncthreads();
    if (tid == 0) {
        float mx = fmaxf(fmaxf(lg[0], lg[1]), fmaxf(lg[2], lg[3]));
        float e0 = __expf(lg[0] - mx), e1 = __expf(lg[1] - mx);
        float e2 = __expf(lg[2] - mx), e3 = __expf(lg[3] - mx);
        float s = e0 + e1 + e2 + e3;
        out[0] = e0 / s; out[1] = e1 / s; out[2] = e2 / s; out[3] = e3 / s;
    }
}

// ---------------- launch ----------------
extern "C" void kernel_launch(void* const* d_in, const int* in_sizes, int n_in,
                              void* d_out, int out_size) {
    const float* x_word  = (const float*)d_in[0];
    const int*   x_index = (const int*)  d_in[1];
    const int*   tree    = (const int*)  d_in[2];
    const float* E       = (const float*)d_in[3];
    const float* Wz      = (const float*)d_in[4];
    const float* Uz      = (const float*)d_in[5];
    const float* bz      = (const float*)d_in[6];
    const float* Wr      = (const float*)d_in[7];
    const float* Ur      = (const float*)d_in[8];
    const float* br      = (const float*)d_in[9];
    const float* Wh      = (const float*)d_in[10];
    const float* Uh      = (const float*)d_in[11];
    const float* bh      = (const float*)d_in[12];
    const float* Wa      = (const float*)d_in[13];
    const float* Wout    = (const float*)d_in[14];
    const float* bout    = (const float*)d_in[15];
    float* out = (float*)d_out;

    const int smemMain = (3 * 64 * UPITCH + 8 * 64) * 4;            // 52736 B
    cudaFuncSetAttribute(k_main, cudaFuncAttributeMaxDynamicSharedMemorySize, smemMain);

    int dev = 0;
    cudaGetDevice(&dev);
    int sms = 0;
    if (cudaDeviceGetAttribute(&sms, cudaDevAttrMultiProcessorCount, dev) != cudaSuccess || sms <= 0)
        sms = 148;
    int nb = 0;
    if (cudaOccupancyMaxActiveBlocksPerMultiprocessor(&nb, k_main, 256, smemMain) != cudaSuccess || nb < 1)
        nb = 1;
    int pgrid = sms * nb;                  // guaranteed co-resident
    if (pgrid > NP / 8) pgrid = NP / 8;
    if (pgrid < LEAFB) pgrid = LEAFB;      // all leaf tiles must be covered
    if (pgrid < 1) pgrid = 1;

    k_prep<<<4 + (NN * H / 4 + 255) / 256, 256>>>(Wz, Wr, Wh, Wa);
    k_transpose<<<3125, 256>>>(E);
    k_embed<<<2048, 256>>>(x_word, x_index);
    k_main<<<pgrid, 256, smemMain>>>(Uz, Ur, Uh, tree, Wz, Wh, bz, br, bh);
    k_rmax<<<256, 256>>>();
    k_final<<<1, 256>>>(Wout, bout, out);
}